// round 5
// baseline (speedup 1.0000x reference)
#include <cuda_runtime.h>
#include <cuda_bf16.h>
#include <cstdint>

#define NN 256
#define LL 256
#define BB 16384

#if defined(__CUDA_ARCH_FEAT_SM103_ALL) || defined(__CUDA_ARCH_FEAT_SM100_ALL) || defined(__CUDA_ARCH_FEAT_SM101_ALL)
#define HAS_TC 1
#else
#define HAS_TC 0
#endif

typedef unsigned long long u64;

// ---------------- scratch ----------------
// transposed coeffs: [n][l] so one thread's layer stream is contiguous
__device__ float2 g_DGt[NN * LL];
__device__ float2 g_OPt[NN * LL];
// B operand stored as PRE-SWIZZLED SMEM tile images, one 32KB tile per k-chunk:
// tile c (c=0..15) holds W'^T rows n=0..511, k = c*32..c*32+31 (SW64 layout).
__device__ __align__(128) __nv_bfloat16 g_Bh[512 * 512];
__device__ __align__(128) __nv_bfloat16 g_Bl[512 * 512];

// ---------------- common helpers ----------------
__device__ __forceinline__ uint32_t smem_u32(const void* p) {
    uint32_t a;
    asm("{ .reg .u64 t; cvta.to.shared.u64 t, %1; cvt.u32.u64 %0, t; }" : "=r"(a) : "l"(p));
    return a;
}
__device__ __forceinline__ float2 cmul(float2 a, float2 b) {
    return make_float2(a.x * b.x - a.y * b.y, a.x * b.y + a.y * b.x);
}
union BU { __nv_bfloat162 h; uint32_t u; };
union F2U { float2 f; u64 u; };

#define FMA_F32X2(d, a, b) \
    asm("fma.rn.f32x2 %0, %1, %2, %0;" : "+l"(d) : "l"(a), "l"(b))
#define MUL_F32X2(d, a, b) \
    asm("mul.rn.f32x2 %0, %1, %2;" : "=l"(d) : "l"(a), "l"(b))
__device__ __forceinline__ u64 pack2(float lo, float hi) {
    u64 r; asm("mov.b64 %0, {%1,%2};" : "=l"(r) : "f"(lo), "f"(hi)); return r;
}
__device__ __forceinline__ u64 dup2(float x) {
    u64 r; asm("mov.b64 %0, {%1,%1};" : "=l"(r) : "f"(x)); return r;
}

// ---------------- tcgen05 / async helpers ----------------
#define TCGEN05_ALLOC(sa, n) \
    asm volatile("tcgen05.alloc.cta_group::1.sync.aligned.shared::cta.b32 [%0], %1;" :: "r"((uint32_t)(sa)), "r"((uint32_t)(n)) : "memory")
#define TCGEN05_DEALLOC(t, n) \
    asm volatile("tcgen05.dealloc.cta_group::1.sync.aligned.b32 %0, %1;" :: "r"(t), "r"((uint32_t)(n)))
#define TCGEN05_RELINQ() \
    asm volatile("tcgen05.relinquish_alloc_permit.cta_group::1.sync.aligned;")
#define TCGEN05_COMMIT(mb) \
    asm volatile("tcgen05.commit.cta_group::1.mbarrier::arrive::one.shared::cluster.b64 [%0];" :: "r"((uint32_t)(mb)) : "memory")
#define TCGEN05_WAIT_LD() asm volatile("tcgen05.wait::ld.sync.aligned;" ::: "memory")
#define TCGEN05_FENCE_AFTER() asm volatile("tcgen05.fence::after_thread_sync;" ::: "memory")
#define FENCE_ASYNC_SHARED() asm volatile("fence.proxy.async.shared::cta;" ::: "memory")

#define MBARRIER_INIT(mb, cnt) \
    asm volatile("mbarrier.init.shared.b64 [%0], %1;" :: "r"((uint32_t)(mb)), "r"((uint32_t)(cnt)) : "memory")
#define MBARRIER_ARRIVE(mb) \
    asm volatile("mbarrier.arrive.shared.b64 _, [%0];" :: "r"((uint32_t)(mb)) : "memory")
#define MBARRIER_EXPECT_TX(mb, tx) \
    asm volatile("mbarrier.arrive.expect_tx.shared.b64 _, [%0], %1;" :: "r"((uint32_t)(mb)), "r"((uint32_t)(tx)) : "memory")
#define MBARRIER_WAIT_PARITY(mb, ph) do { \
    uint32_t _mb = (uint32_t)(mb), _ph = (uint32_t)(ph), _done; \
    asm volatile("{\n\t.reg .pred p;\n\tmbarrier.try_wait.parity.acquire.cta.shared::cta.b64 p, [%1], %2;\n\tselp.b32 %0, 1, 0, p;\n\t}" \
        : "=r"(_done) : "r"(_mb), "r"(_ph) : "memory"); \
    if (!_done) { \
        asm volatile("{\n\t.reg .pred P1;\n\tWL_%=:\n\tmbarrier.try_wait.parity.acquire.cta.shared::cta.b64 P1, [%0], %1, 0x989680;\n\t@P1 bra.uni WD_%=;\n\tbra.uni WL_%=;\n\tWD_%=:\n\t}" \
            :: "r"(_mb), "r"(_ph) : "memory"); \
    } } while (0)

#define CP_ASYNC_BULK(dst, src, bytes, mb) \
    asm volatile("cp.async.bulk.shared::cluster.global.mbarrier::complete_tx::bytes [%0], [%1], %2, [%3];" \
        :: "r"((uint32_t)(dst)), "l"(src), "r"((uint32_t)(bytes)), "r"((uint32_t)(mb)) : "memory")

#define TCGEN05_LD_32X32B_X32(r, ta) \
    asm volatile("tcgen05.ld.sync.aligned.32x32b.x32.b32 " \
        "{%0,%1,%2,%3,%4,%5,%6,%7,%8,%9,%10,%11,%12,%13,%14,%15," \
        "%16,%17,%18,%19,%20,%21,%22,%23,%24,%25,%26,%27,%28,%29,%30,%31}, [%32];" \
        : "=r"((r)[0]), "=r"((r)[1]), "=r"((r)[2]), "=r"((r)[3]), "=r"((r)[4]), "=r"((r)[5]), "=r"((r)[6]), "=r"((r)[7]), \
          "=r"((r)[8]), "=r"((r)[9]), "=r"((r)[10]), "=r"((r)[11]), "=r"((r)[12]), "=r"((r)[13]), "=r"((r)[14]), "=r"((r)[15]), \
          "=r"((r)[16]), "=r"((r)[17]), "=r"((r)[18]), "=r"((r)[19]), "=r"((r)[20]), "=r"((r)[21]), "=r"((r)[22]), "=r"((r)[23]), \
          "=r"((r)[24]), "=r"((r)[25]), "=r"((r)[26]), "=r"((r)[27]), "=r"((r)[28]), "=r"((r)[29]), "=r"((r)[30]), "=r"((r)[31]) \
        : "r"(ta))

#define SWZ64(o) ((o) ^ (((o) >> 3) & 0x30))

#if HAS_TC
__device__ __forceinline__ uint32_t elect_one_pred() {
    uint32_t p;
    asm volatile("{\n\t.reg .pred p;\n\telect.sync _|p, 0xFFFFFFFF;\n\tselp.b32 %0, 1, 0, p;\n\t}" : "=r"(p));
    return p;
}
// SW64 K-major descriptor: layout=4, version=1, SBO=32 (512B per 8-row group), LBO=1 (16B)
__device__ __forceinline__ uint64_t make_desc_sw64(uint32_t base) {
    return ((uint64_t)4 << 61) | ((uint64_t)1 << 46) | ((uint64_t)32 << 32) | ((uint64_t)1 << 16)
         | (uint64_t)((base >> 4) & 0x3FFF);
}
__device__ __forceinline__ void mma_f16_ss_cg1(uint32_t d, uint64_t ad, uint64_t bd,
                                               uint32_t idesc, uint32_t en) {
    asm volatile(
        "{\n\t.reg .pred p;\n\tsetp.ne.u32 p, %5, 0;\n\t"
        "tcgen05.mma.cta_group::1.kind::f16 [%0], %1, %2, %3, {%4,%4,%4,%4}, p;\n\t}"
        :: "r"(d), "l"(ad), "l"(bd), "r"(idesc), "r"(0u), "r"(en) : "memory");
}
#endif

// ---------------- kernel 1: per-layer MZI coefficients (SMEM-shared sincos) ----------------
__global__ void coeff_kernel(const float* __restrict__ theta,
                             const float* __restrict__ phi) {
    __shared__ float2 ips[NN];
    __shared__ float2 eps[NN];
    int l = blockIdx.x;
    int n = threadIdx.x;
    const float* th = theta + l * (NN / 2);
    const float* ph = phi + l * (NN / 2);

    {
        float ang = 0.5f * th[n >> 1];
        if (n & 1) ang = -ang;
        float s, c; sincosf(ang, &s, &c);
        ips[n] = make_float2(c, s);
        if (n & 1) eps[n] = make_float2(1.f, 0.f);
        else { float s2, c2; sincosf(ph[n >> 1], &s2, &c2); eps[n] = make_float2(c2, s2); }
    }
    __syncthreads();

    int nm = (n - 1) & (NN - 1), np = (n + 1) & (NN - 1);
    float2 p0 = ips[nm], p1 = ips[n], p2 = ips[np];
    float2 v = make_float2(2.f * p1.x - p2.x - p0.x, 2.f * p1.y - p2.y - p0.y);
    float2 u = make_float2(2.f * p1.x + p2.x + p0.x, 2.f * p1.y + p2.y + p0.y);
    float2 en = eps[n], ep = eps[nm];

    float2 diag = cmul(en, v); diag.x *= 0.25f; diag.y *= 0.25f;
    float2 iu = make_float2(-u.y, u.x);
    float2 off = cmul(ep, iu); off.x *= 0.25f; off.y *= 0.25f;

    g_DGt[n * LL + l] = diag;             // transposed: thread-stream contiguous in l
    g_OPt[(n ^ 1) * LL + l] = off;        // partner-indexed
}

// ---------------- kernel 2: compose W (contiguous coeff stream, deep prefetch) ----------------
#define RB 2
__global__ __launch_bounds__(NN) void build_w_kernel(const float* __restrict__ gamma) {
    __shared__ float2 bufA[RB][NN];
    __shared__ float2 bufB[RB][NN];
    int i = threadIdx.x;
    int r0 = blockIdx.x * RB;

#pragma unroll
    for (int r = 0; r < RB; r++) {
        int j = r0 + r;
        float2 v = make_float2(0.f, 0.f);
        if (i == j) { float s, c; sincosf(gamma[j], &s, &c); v = make_float2(c, s); }
        bufA[r][i] = v;
    }

    const float4* dgp = (const float4*)(g_DGt + (size_t)i * LL);   // [l/2] -> layers l, l+1
    const float4* opp = (const float4*)(g_OPt + (size_t)i * LL);
    float4 dg01 = dgp[0], op01 = opp[0];
    float4 dg23 = dgp[1], op23 = opp[1];
    __syncthreads();

    float2 (*A)[NN] = bufA;
    float2 (*Bx)[NN] = bufB;

    for (int l = 0; l < LL; l += 2) {
        float4 dgc = dg01, opc = op01;
        dg01 = dg23; op01 = op23;
        if (l < LL - 4) { dg23 = dgp[l / 2 + 2]; op23 = opp[l / 2 + 2]; }

        // ---- layer l (even): shift = 0 for l==0, else -1
        {
            int s = (l == 0) ? 0 : -1;
            int ia = (i + s) & (NN - 1);
            int ib = ((i ^ 1) + s) & (NN - 1);
            u64 d1 = pack2(dgc.x, dgc.y), d2 = pack2(-dgc.y, dgc.x);
            u64 o1 = pack2(opc.x, opc.y), o2 = pack2(-opc.y, opc.x);
#pragma unroll
            for (int r = 0; r < RB; r++) {
                float2 t = A[r][ia];
                float2 u = A[r][ib];
                u64 w;
                MUL_F32X2(w, dup2(t.x), d1);
                FMA_F32X2(w, dup2(t.y), d2);
                FMA_F32X2(w, dup2(u.x), o1);
                FMA_F32X2(w, dup2(u.y), o2);
                F2U cv; cv.u = w;
                Bx[r][i] = cv.f;
            }
            __syncthreads();
            float2 (*tmp)[NN] = A; A = Bx; Bx = tmp;
        }
        // ---- layer l+1 (odd): shift = +1
        {
            int ia = (i + 1) & (NN - 1);
            int ib = ((i ^ 1) + 1) & (NN - 1);
            u64 d1 = pack2(dgc.z, dgc.w), d2 = pack2(-dgc.w, dgc.z);
            u64 o1 = pack2(opc.z, opc.w), o2 = pack2(-opc.w, opc.z);
#pragma unroll
            for (int r = 0; r < RB; r++) {
                float2 t = A[r][ia];
                float2 u = A[r][ib];
                u64 w;
                MUL_F32X2(w, dup2(t.x), d1);
                FMA_F32X2(w, dup2(t.y), d2);
                FMA_F32X2(w, dup2(u.x), o1);
                FMA_F32X2(w, dup2(u.y), o2);
                F2U cv; cv.u = w;
                Bx[r][i] = cv.f;
            }
            __syncthreads();
            float2 (*tmp)[NN] = A; A = Bx; Bx = tmp;
        }
    }

    // store element (nrow, kcol) of W'^T into the pre-swizzled chunk image
    auto store_b = [](int nrow, int kcol, __nv_bfloat16 vh, __nv_bfloat16 vl) {
        uint32_t c = (uint32_t)kcol >> 5;
        uint32_t off = c * 32768u + SWZ64((uint32_t)(nrow * 64 + (kcol & 31) * 2));
        *(__nv_bfloat16*)((char*)g_Bh + off) = vh;
        *(__nv_bfloat16*)((char*)g_Bl + off) = vl;
    };

    int src = (i - 1) & (NN - 1);
#pragma unroll
    for (int r = 0; r < RB; r++) {
        float2 w = A[r][src];        // W[k][n], k = r0+r, n = i
        int k = r0 + r, n = i;
        __nv_bfloat16 hr = __float2bfloat16(w.x);
        __nv_bfloat16 lr = __float2bfloat16(w.x - __bfloat162float(hr));
        __nv_bfloat16 hi = __float2bfloat16(w.y);
        __nv_bfloat16 li = __float2bfloat16(w.y - __bfloat162float(hi));
        __nv_bfloat16 nhi = __hneg(hi), nli = __hneg(li);
        // B[n][k]=Wr, B[n][256+k]=-Wi, B[256+n][k]=Wi, B[256+n][256+k]=Wr
        store_b(n, k, hr, lr);
        store_b(n, 256 + k, nhi, nli);
        store_b(256 + n, k, hi, li);
        store_b(256 + n, 256 + k, hr, lr);
    }
}

// ---------------- kernel 2.5: no-op spacer (keeps ncu capture on gemm) ----------------
__global__ void probe_kernel() {}

// ---------------- kernel 3: tcgen05 bf16-split GEMM ----------------
#define KC 32
#define SMEM_TMEM 0
#define MB_FULL(s)  (16 + (s) * 8)
#define MB_EMPTY(s) (32 + (s) * 8)
#define MB_DONE     48
#define STAGE_SZ    81920
#define STAGE_BASE(s) (1024 + (s) * STAGE_SZ)
#define A_HI_OFF 0
#define A_LO_OFF 8192
#define B_HI_OFF 16384
#define B_LO_OFF 49152
#define SMEM_TOTAL (1024 + 2 * STAGE_SZ)

__global__ __launch_bounds__(256, 1)
void gemm_tc_kernel(const float* __restrict__ xre, const float* __restrict__ xim,
                    float* __restrict__ out) {
#if HAS_TC
    extern __shared__ char smem[];
    const uint32_t sb = smem_u32(smem);
    int tid = threadIdx.x, wid = tid >> 5, lane = tid & 31;
    int m0 = blockIdx.x * 128;

    if (wid == 4) TCGEN05_ALLOC(sb + SMEM_TMEM, 512);
    if (tid == 0) {
        MBARRIER_INIT(sb + MB_FULL(0), 5);   // 4 A-warps + 1 expect_tx arrive
        MBARRIER_INIT(sb + MB_FULL(1), 5);
        MBARRIER_INIT(sb + MB_EMPTY(0), 1);
        MBARRIER_INIT(sb + MB_EMPTY(1), 1);
        MBARRIER_INIT(sb + MB_DONE, 1);
    }
    __syncthreads();
    uint32_t tmem;
    asm volatile("ld.shared.b32 %0, [%1];" : "=r"(tmem) : "r"(sb + SMEM_TMEM));

    if (wid < 4) {
        // ---- A producer (coalesced): load X[m0:m0+128, kc:kc+32] fp32 -> bf16 hi/lo -> STS SW64
        for (int it = 0; it < 16; ++it) {
            int s = it & 1;
            if (it >= 2) MBARRIER_WAIT_PARITY(sb + MB_EMPTY(s), ((it >> 1) - 1) & 1);
            const float* plane = (it < 8) ? xre : xim;
            int kc = (it & 7) * KC;
            uint32_t ahi = sb + STAGE_BASE(s) + A_HI_OFF;
            uint32_t alo = sb + STAGE_BASE(s) + A_LO_OFF;
#pragma unroll
            for (int j = 0; j < 8; ++j) {
                int g = j * 128 + tid;
                int r = g >> 3, f4 = g & 7;
                float4 v = *(const float4*)(plane + (size_t)(m0 + r) * NN + kc + f4 * 4);
                BU h0, h1, l0, l1;
                h0.h = __floats2bfloat162_rn(v.x, v.y);
                h1.h = __floats2bfloat162_rn(v.z, v.w);
                float2 f0 = __bfloat1622float2(h0.h), f1 = __bfloat1622float2(h1.h);
                l0.h = __floats2bfloat162_rn(v.x - f0.x, v.y - f0.y);
                l1.h = __floats2bfloat162_rn(v.z - f1.x, v.w - f1.y);
                uint32_t off = SWZ64((uint32_t)(r * 64 + f4 * 8));
                asm volatile("st.shared.v2.b32 [%0], {%1,%2};" :: "r"(ahi + off), "r"(h0.u), "r"(h1.u) : "memory");
                asm volatile("st.shared.v2.b32 [%0], {%1,%2};" :: "r"(alo + off), "r"(l0.u), "r"(l1.u) : "memory");
            }
            FENCE_ASYNC_SHARED();
            __syncwarp();
            if (lane == 0) MBARRIER_ARRIVE(sb + MB_FULL(s));
        }
    } else if (wid == 5) {
        // ---- B producer: one bulk-copy pair per stage from pre-swizzled tile images
        for (int it = 0; it < 16; ++it) {
            int s = it & 1;
            if (it >= 2) MBARRIER_WAIT_PARITY(sb + MB_EMPTY(s), ((it >> 1) - 1) & 1);
            if (elect_one_pred()) {
                uint32_t mb = sb + MB_FULL(s);
                MBARRIER_EXPECT_TX(mb, 65536);
                const char* srch = (const char*)g_Bh + (size_t)it * 32768;
                const char* srcl = (const char*)g_Bl + (size_t)it * 32768;
                CP_ASYNC_BULK(sb + STAGE_BASE(s) + B_HI_OFF, srch, 32768, mb);
                CP_ASYNC_BULK(sb + STAGE_BASE(s) + B_LO_OFF, srcl, 32768, mb);
            }
        }
    } else if (wid == 4) {
        // ---- MMA warp
        const uint32_t IDESC = (1u << 4) | (1u << 7) | (1u << 10) | (32u << 17) | (8u << 24);
        for (int it = 0; it < 16; ++it) {
            int s = it & 1;
            MBARRIER_WAIT_PARITY(sb + MB_FULL(s), (it >> 1) & 1);
            if (elect_one_pred()) {
                uint32_t stage = sb + STAGE_BASE(s);
                uint64_t ah = make_desc_sw64(stage + A_HI_OFF);
                uint64_t al = make_desc_sw64(stage + A_LO_OFF);
                uint64_t bh = make_desc_sw64(stage + B_HI_OFF);
                uint64_t bl = make_desc_sw64(stage + B_LO_OFF);
#pragma unroll
                for (int seg = 0; seg < 3; ++seg) {
                    uint64_t ad = (seg == 2) ? al : ah;
                    uint64_t bd = (seg == 1) ? bl : bh;
#pragma unroll
                    for (int kk = 0; kk < 2; ++kk) {
#pragma unroll
                        for (int nh = 0; nh < 2; ++nh) {
                            uint32_t en = !(it == 0 && seg == 0 && kk == 0);
                            mma_f16_ss_cg1(tmem + nh * 256, ad + kk * 2,
                                           bd + (uint64_t)nh * 1024 + kk * 2, IDESC, en);
                        }
                    }
                }
                TCGEN05_COMMIT((it == 15) ? (sb + MB_DONE) : (sb + MB_EMPTY(s)));
            }
        }
    }
    // warps 6,7: fall through to epilogue wait

    // ---- epilogue: WG0 -> re plane (cols 0-255), WG1 -> im plane (cols 256-511)
    MBARRIER_WAIT_PARITY(sb + MB_DONE, 0);
    TCGEN05_FENCE_AFTER();
    {
        int wg = tid >> 7;
        int wt = tid & 127;
        int m = m0 + wt;
        float* dst = out + (size_t)wg * BB * NN + (size_t)m * NN;
        uint32_t colbase = tmem + wg * 256;
#pragma unroll
        for (int c = 0; c < 8; ++c) {
            uint32_t r[32];
            TCGEN05_LD_32X32B_X32(r, colbase + c * 32);
            TCGEN05_WAIT_LD();
            float4* d4 = (float4*)(dst + c * 32);
#pragma unroll
            for (int q = 0; q < 8; ++q)
                d4[q] = make_float4(__uint_as_float(r[4 * q]), __uint_as_float(r[4 * q + 1]),
                                    __uint_as_float(r[4 * q + 2]), __uint_as_float(r[4 * q + 3]));
        }
    }
    __syncthreads();
    if (wid == 4) {
        TCGEN05_RELINQ();
        TCGEN05_DEALLOC(tmem, 512);
    }
#endif  // HAS_TC
}

// ---------------- launch ----------------
extern "C" void kernel_launch(void* const* d_in, const int* in_sizes, int n_in,
                              void* d_out, int out_size) {
    const float* x_re  = (const float*)d_in[0];
    const float* x_im  = (const float*)d_in[1];
    const float* theta = (const float*)d_in[2];
    const float* phi   = (const float*)d_in[3];
    const float* gamma = (const float*)d_in[4];
    float* out = (float*)d_out;

    cudaFuncSetAttribute(gemm_tc_kernel, cudaFuncAttributeMaxDynamicSharedMemorySize, SMEM_TOTAL);

    coeff_kernel<<<LL, NN>>>(theta, phi);
    build_w_kernel<<<NN / RB, NN>>>(gamma);
    probe_kernel<<<1, 32>>>();
    gemm_tc_kernel<<<BB / 128, 256, SMEM_TOTAL>>>(x_re, x_im, out);
}

// round 6
// speedup vs baseline: 1.2322x; 1.2322x over previous
#include <cuda_runtime.h>
#include <cuda_bf16.h>
#include <cstdint>

#define NN 256
#define LL 256
#define BB 16384

#if defined(__CUDA_ARCH_FEAT_SM103_ALL) || defined(__CUDA_ARCH_FEAT_SM100_ALL) || defined(__CUDA_ARCH_FEAT_SM101_ALL)
#define HAS_TC 1
#else
#define HAS_TC 0
#endif

typedef unsigned long long u64;

// ---------------- scratch ----------------
__device__ float2 g_DG[LL * NN];   // [l][n] — coalesced
__device__ float2 g_OP[LL * NN];
// Deduplicated B images: Wr[k][n] and Wi[k][n] as bf16 hi/lo, stored as
// PRE-SWIZZLED SMEM tile images per 32-k chunk (chunk c: 16KB, SW64 layout).
__device__ __align__(128) __nv_bfloat16 g_Wrh[256 * 256];
__device__ __align__(128) __nv_bfloat16 g_Wrl[256 * 256];
__device__ __align__(128) __nv_bfloat16 g_Wih[256 * 256];
__device__ __align__(128) __nv_bfloat16 g_Wil[256 * 256];

// ---------------- common helpers ----------------
__device__ __forceinline__ uint32_t smem_u32(const void* p) {
    uint32_t a;
    asm("{ .reg .u64 t; cvta.to.shared.u64 t, %1; cvt.u32.u64 %0, t; }" : "=r"(a) : "l"(p));
    return a;
}
__device__ __forceinline__ float2 cmul(float2 a, float2 b) {
    return make_float2(a.x * b.x - a.y * b.y, a.x * b.y + a.y * b.x);
}
union BU { __nv_bfloat162 h; uint32_t u; };
union F2U { float2 f; u64 u; };

#define FMA_F32X2(d, a, b) \
    asm("fma.rn.f32x2 %0, %1, %2, %0;" : "+l"(d) : "l"(a), "l"(b))
#define MUL_F32X2(d, a, b) \
    asm("mul.rn.f32x2 %0, %1, %2;" : "=l"(d) : "l"(a), "l"(b))
__device__ __forceinline__ u64 pack2(float lo, float hi) {
    u64 r; asm("mov.b64 %0, {%1,%2};" : "=l"(r) : "f"(lo), "f"(hi)); return r;
}
__device__ __forceinline__ u64 dup2(float x) {
    u64 r; asm("mov.b64 %0, {%1,%1};" : "=l"(r) : "f"(x)); return r;
}

// ---------------- tcgen05 / async helpers ----------------
#define TCGEN05_ALLOC(sa, n) \
    asm volatile("tcgen05.alloc.cta_group::1.sync.aligned.shared::cta.b32 [%0], %1;" :: "r"((uint32_t)(sa)), "r"((uint32_t)(n)) : "memory")
#define TCGEN05_DEALLOC(t, n) \
    asm volatile("tcgen05.dealloc.cta_group::1.sync.aligned.b32 %0, %1;" :: "r"(t), "r"((uint32_t)(n)))
#define TCGEN05_RELINQ() \
    asm volatile("tcgen05.relinquish_alloc_permit.cta_group::1.sync.aligned;")
#define TCGEN05_COMMIT(mb) \
    asm volatile("tcgen05.commit.cta_group::1.mbarrier::arrive::one.shared::cluster.b64 [%0];" :: "r"((uint32_t)(mb)) : "memory")
#define TCGEN05_WAIT_LD() asm volatile("tcgen05.wait::ld.sync.aligned;" ::: "memory")
#define TCGEN05_FENCE_AFTER() asm volatile("tcgen05.fence::after_thread_sync;" ::: "memory")
#define FENCE_ASYNC_SHARED() asm volatile("fence.proxy.async.shared::cta;" ::: "memory")

#define MBARRIER_INIT(mb, cnt) \
    asm volatile("mbarrier.init.shared.b64 [%0], %1;" :: "r"((uint32_t)(mb)), "r"((uint32_t)(cnt)) : "memory")
#define MBARRIER_ARRIVE(mb) \
    asm volatile("mbarrier.arrive.shared.b64 _, [%0];" :: "r"((uint32_t)(mb)) : "memory")
#define MBARRIER_EXPECT_TX(mb, tx) \
    asm volatile("mbarrier.arrive.expect_tx.shared.b64 _, [%0], %1;" :: "r"((uint32_t)(mb)), "r"((uint32_t)(tx)) : "memory")
#define MBARRIER_WAIT_PARITY(mb, ph) do { \
    uint32_t _mb = (uint32_t)(mb), _ph = (uint32_t)(ph), _done; \
    asm volatile("{\n\t.reg .pred p;\n\tmbarrier.try_wait.parity.acquire.cta.shared::cta.b64 p, [%1], %2;\n\tselp.b32 %0, 1, 0, p;\n\t}" \
        : "=r"(_done) : "r"(_mb), "r"(_ph) : "memory"); \
    if (!_done) { \
        asm volatile("{\n\t.reg .pred P1;\n\tWL_%=:\n\tmbarrier.try_wait.parity.acquire.cta.shared::cta.b64 P1, [%0], %1, 0x989680;\n\t@P1 bra.uni WD_%=;\n\tbra.uni WL_%=;\n\tWD_%=:\n\t}" \
            :: "r"(_mb), "r"(_ph) : "memory"); \
    } } while (0)

#define CP_ASYNC_BULK(dst, src, bytes, mb) \
    asm volatile("cp.async.bulk.shared::cluster.global.mbarrier::complete_tx::bytes [%0], [%1], %2, [%3];" \
        :: "r"((uint32_t)(dst)), "l"(src), "r"((uint32_t)(bytes)), "r"((uint32_t)(mb)) : "memory")

#define TCGEN05_LD_32X32B_X32(r, ta) \
    asm volatile("tcgen05.ld.sync.aligned.32x32b.x32.b32 " \
        "{%0,%1,%2,%3,%4,%5,%6,%7,%8,%9,%10,%11,%12,%13,%14,%15," \
        "%16,%17,%18,%19,%20,%21,%22,%23,%24,%25,%26,%27,%28,%29,%30,%31}, [%32];" \
        : "=r"((r)[0]), "=r"((r)[1]), "=r"((r)[2]), "=r"((r)[3]), "=r"((r)[4]), "=r"((r)[5]), "=r"((r)[6]), "=r"((r)[7]), \
          "=r"((r)[8]), "=r"((r)[9]), "=r"((r)[10]), "=r"((r)[11]), "=r"((r)[12]), "=r"((r)[13]), "=r"((r)[14]), "=r"((r)[15]), \
          "=r"((r)[16]), "=r"((r)[17]), "=r"((r)[18]), "=r"((r)[19]), "=r"((r)[20]), "=r"((r)[21]), "=r"((r)[22]), "=r"((r)[23]), \
          "=r"((r)[24]), "=r"((r)[25]), "=r"((r)[26]), "=r"((r)[27]), "=r"((r)[28]), "=r"((r)[29]), "=r"((r)[30]), "=r"((r)[31]) \
        : "r"(ta))

#define SWZ64(o) ((o) ^ (((o) >> 3) & 0x30))

#if HAS_TC
__device__ __forceinline__ uint32_t elect_one_pred() {
    uint32_t p;
    asm volatile("{\n\t.reg .pred p;\n\telect.sync _|p, 0xFFFFFFFF;\n\tselp.b32 %0, 1, 0, p;\n\t}" : "=r"(p));
    return p;
}
// SW64 K-major descriptor: layout=4, version=1, SBO=32 (512B per 8-row group), LBO=1 (16B)
__device__ __forceinline__ uint64_t make_desc_sw64(uint32_t base) {
    return ((uint64_t)4 << 61) | ((uint64_t)1 << 46) | ((uint64_t)32 << 32) | ((uint64_t)1 << 16)
         | (uint64_t)((base >> 4) & 0x3FFF);
}
__device__ __forceinline__ void mma_f16_ss_cg1(uint32_t d, uint64_t ad, uint64_t bd,
                                               uint32_t idesc, uint32_t en) {
    asm volatile(
        "{\n\t.reg .pred p;\n\tsetp.ne.u32 p, %5, 0;\n\t"
        "tcgen05.mma.cta_group::1.kind::f16 [%0], %1, %2, %3, {%4,%4,%4,%4}, p;\n\t}"
        :: "r"(d), "l"(ad), "l"(bd), "r"(idesc), "r"(0u), "r"(en) : "memory");
}
#endif

// ---------------- kernel 1: per-layer MZI coefficients ----------------
__global__ void coeff_kernel(const float* __restrict__ theta,
                             const float* __restrict__ phi) {
    __shared__ float2 ips[NN];
    __shared__ float2 eps[NN];
    int l = blockIdx.x;
    int n = threadIdx.x;
    const float* th = theta + l * (NN / 2);
    const float* ph = phi + l * (NN / 2);

    {
        float ang = 0.5f * th[n >> 1];
        if (n & 1) ang = -ang;
        float s, c; sincosf(ang, &s, &c);
        ips[n] = make_float2(c, s);
        if (n & 1) eps[n] = make_float2(1.f, 0.f);
        else { float s2, c2; sincosf(ph[n >> 1], &s2, &c2); eps[n] = make_float2(c2, s2); }
    }
    __syncthreads();

    int nm = (n - 1) & (NN - 1), np = (n + 1) & (NN - 1);
    float2 p0 = ips[nm], p1 = ips[n], p2 = ips[np];
    float2 v = make_float2(2.f * p1.x - p2.x - p0.x, 2.f * p1.y - p2.y - p0.y);
    float2 u = make_float2(2.f * p1.x + p2.x + p0.x, 2.f * p1.y + p2.y + p0.y);
    float2 en = eps[n], ep = eps[nm];

    float2 diag = cmul(en, v); diag.x *= 0.25f; diag.y *= 0.25f;
    float2 iu = make_float2(-u.y, u.x);
    float2 off = cmul(ep, iu); off.x *= 0.25f; off.y *= 0.25f;

    g_DG[l * NN + n] = diag;
    g_OP[l * NN + (n ^ 1)] = off;
}

// ---------------- kernel 2: compose W ([l][n] coalesced, 4-deep prefetch queue) ----------------
#define RB 2
__global__ __launch_bounds__(NN) void build_w_kernel(const float* __restrict__ gamma) {
    __shared__ float2 bufA[RB][NN];
    __shared__ float2 bufB[RB][NN];
    int i = threadIdx.x;
    int r0 = blockIdx.x * RB;

#pragma unroll
    for (int r = 0; r < RB; r++) {
        int j = r0 + r;
        float2 v = make_float2(0.f, 0.f);
        if (i == j) { float s, c; sincosf(gamma[j], &s, &c); v = make_float2(c, s); }
        bufA[r][i] = v;
    }

    // 4-deep register prefetch queue over [l][n] layout (coalesced LDGs)
    float2 dq[4], oq[4];
#pragma unroll
    for (int p = 0; p < 4; p++) { dq[p] = g_DG[p * NN + i]; oq[p] = g_OP[p * NN + i]; }
    __syncthreads();

    float2 (*A)[NN] = bufA;
    float2 (*Bx)[NN] = bufB;

    for (int lq = 0; lq < LL; lq += 4) {
#pragma unroll
        for (int p = 0; p < 4; p++) {
            int l = lq + p;
            float2 d = dq[p], o = oq[p];
            if (lq + 4 < LL) {   // refill slot p with layer l+4
                dq[p] = g_DG[(l + 4) * NN + i];
                oq[p] = g_OP[(l + 4) * NN + i];
            }
            int s = (l == 0) ? 0 : ((p & 1) ? 1 : -1);   // parity of l == parity of p
            int ia = (i + s) & (NN - 1);
            int ib = ((i ^ 1) + s) & (NN - 1);
            u64 d1 = pack2(d.x, d.y), d2 = pack2(-d.y, d.x);
            u64 o1 = pack2(o.x, o.y), o2 = pack2(-o.y, o.x);
#pragma unroll
            for (int r = 0; r < RB; r++) {
                float2 t = A[r][ia];
                float2 u = A[r][ib];
                u64 w;
                MUL_F32X2(w, dup2(t.x), d1);
                FMA_F32X2(w, dup2(t.y), d2);
                FMA_F32X2(w, dup2(u.x), o1);
                FMA_F32X2(w, dup2(u.y), o2);
                F2U cv; cv.u = w;
                Bx[r][i] = cv.f;
            }
            __syncthreads();
            float2 (*tmp)[NN] = A; A = Bx; Bx = tmp;
        }
    }

    // store element (n=i, k=r0+r) of Wr/Wi into pre-swizzled 32-k chunk images
    auto store_b = [](__nv_bfloat16* img, int n, int k, __nv_bfloat16 v) {
        uint32_t off = ((uint32_t)k >> 5) * 16384u + SWZ64((uint32_t)(n * 64 + (k & 31) * 2));
        *(__nv_bfloat16*)((char*)img + off) = v;
    };

    int src = (i - 1) & (NN - 1);
#pragma unroll
    for (int r = 0; r < RB; r++) {
        float2 w = A[r][src];        // W[k][n], k = r0+r, n = i
        int k = r0 + r, n = i;
        __nv_bfloat16 hr = __float2bfloat16(w.x);
        __nv_bfloat16 lr = __float2bfloat16(w.x - __bfloat162float(hr));
        __nv_bfloat16 hi = __float2bfloat16(w.y);
        __nv_bfloat16 li = __float2bfloat16(w.y - __bfloat162float(hi));
        store_b(g_Wrh, n, k, hr);
        store_b(g_Wrl, n, k, lr);
        store_b(g_Wih, n, k, hi);
        store_b(g_Wil, n, k, li);
    }
}

// ---------------- kernel 2.5: no-op spacer (keeps ncu capture on gemm) ----------------
__global__ void probe_kernel() {}

// ---------------- kernel 3: tcgen05 bf16-split GEMM, deduped B ----------------
// Y = X*W complex via D0 = Yr (tmem 0-255), D1 = Yi (tmem 256-511).
// Per 32-k stage: A tiles Xr_h/l, Xi_h/l, nXi_h/l (SW64, 8KB each);
// B tiles Wr_h/l, Wi_h/l (SW64, 16KB each).
#define KC 32
#define SMEM_TMEM 0
#define MB_FULL(s)  (16 + (s) * 8)
#define MB_EMPTY(s) (32 + (s) * 8)
#define MB_DONE     48
#define XR_H 0
#define XR_L 8192
#define XI_H 16384
#define XI_L 24576
#define NXI_H 32768
#define NXI_L 40960
#define WR_H 49152
#define WR_L 65536
#define WI_H 81920
#define WI_L 98304
#define STAGE_SZ 114688
#define STAGE_BASE(s) (1024 + (s) * STAGE_SZ)
#define SMEM_TOTAL (1024 + 2 * STAGE_SZ)

__global__ __launch_bounds__(256, 1)
void gemm_tc_kernel(const float* __restrict__ xre, const float* __restrict__ xim,
                    float* __restrict__ out) {
#if HAS_TC
    extern __shared__ char smem[];
    const uint32_t sb = smem_u32(smem);
    int tid = threadIdx.x, wid = tid >> 5, lane = tid & 31;
    int m0 = blockIdx.x * 128;

    if (wid == 4) TCGEN05_ALLOC(sb + SMEM_TMEM, 512);
    if (tid == 0) {
        MBARRIER_INIT(sb + MB_FULL(0), 5);   // 4 A-warps + B expect_tx arrive
        MBARRIER_INIT(sb + MB_FULL(1), 5);
        MBARRIER_INIT(sb + MB_EMPTY(0), 1);
        MBARRIER_INIT(sb + MB_EMPTY(1), 1);
        MBARRIER_INIT(sb + MB_DONE, 1);
    }
    __syncthreads();
    uint32_t tmem;
    asm volatile("ld.shared.b32 %0, [%1];" : "=r"(tmem) : "r"(sb + SMEM_TMEM));

    if (wid < 4) {
        // ---- A producer: both planes per stage; coalesced float4 LDG -> bf16 hi/lo (+negated Xi)
        for (int it = 0; it < 8; ++it) {
            int s = it & 1;
            if (it >= 2) MBARRIER_WAIT_PARITY(sb + MB_EMPTY(s), ((it >> 1) - 1) & 1);
            int kc = it * KC;
            uint32_t stage = sb + STAGE_BASE(s);
#pragma unroll
            for (int pl = 0; pl < 2; ++pl) {
                const float* plane = pl ? xim : xre;
                uint32_t hdst = stage + (pl ? XI_H : XR_H);
                uint32_t ldst = stage + (pl ? XI_L : XR_L);
#pragma unroll
                for (int j = 0; j < 8; ++j) {
                    int g = j * 128 + tid;
                    int r = g >> 3, f4 = g & 7;
                    float4 v = *(const float4*)(plane + (size_t)(m0 + r) * NN + kc + f4 * 4);
                    BU h0, h1, l0, l1;
                    h0.h = __floats2bfloat162_rn(v.x, v.y);
                    h1.h = __floats2bfloat162_rn(v.z, v.w);
                    float2 f0 = __bfloat1622float2(h0.h), f1 = __bfloat1622float2(h1.h);
                    l0.h = __floats2bfloat162_rn(v.x - f0.x, v.y - f0.y);
                    l1.h = __floats2bfloat162_rn(v.z - f1.x, v.w - f1.y);
                    uint32_t off = SWZ64((uint32_t)(r * 64 + f4 * 8));
                    asm volatile("st.shared.v2.b32 [%0], {%1,%2};" :: "r"(hdst + off), "r"(h0.u), "r"(h1.u) : "memory");
                    asm volatile("st.shared.v2.b32 [%0], {%1,%2};" :: "r"(ldst + off), "r"(l0.u), "r"(l1.u) : "memory");
                    if (pl) {   // negated Xi copies
                        uint32_t nh0 = h0.u ^ 0x80008000u, nh1 = h1.u ^ 0x80008000u;
                        uint32_t nl0 = l0.u ^ 0x80008000u, nl1 = l1.u ^ 0x80008000u;
                        asm volatile("st.shared.v2.b32 [%0], {%1,%2};" :: "r"(stage + NXI_H + off), "r"(nh0), "r"(nh1) : "memory");
                        asm volatile("st.shared.v2.b32 [%0], {%1,%2};" :: "r"(stage + NXI_L + off), "r"(nl0), "r"(nl1) : "memory");
                    }
                }
            }
            FENCE_ASYNC_SHARED();
            __syncwarp();
            if (lane == 0) MBARRIER_ARRIVE(sb + MB_FULL(s));
        }
    } else if (wid == 5) {
        // ---- B producer: 4 bulk copies (16KB) per stage from pre-swizzled chunk images
        for (int it = 0; it < 8; ++it) {
            int s = it & 1;
            if (it >= 2) MBARRIER_WAIT_PARITY(sb + MB_EMPTY(s), ((it >> 1) - 1) & 1);
            if (elect_one_pred()) {
                uint32_t mb = sb + MB_FULL(s);
                uint32_t stage = sb + STAGE_BASE(s);
                size_t co = (size_t)it * 16384;
                MBARRIER_EXPECT_TX(mb, 65536);
                CP_ASYNC_BULK(stage + WR_H, (const char*)g_Wrh + co, 16384, mb);
                CP_ASYNC_BULK(stage + WR_L, (const char*)g_Wrl + co, 16384, mb);
                CP_ASYNC_BULK(stage + WI_H, (const char*)g_Wih + co, 16384, mb);
                CP_ASYNC_BULK(stage + WI_L, (const char*)g_Wil + co, 16384, mb);
            }
        }
    } else if (wid == 4) {
        // ---- MMA warp: 12 groups/stage, N=256 each; D0=Yr, D1=Yi
        const uint32_t IDESC = (1u << 4) | (1u << 7) | (1u << 10) | (32u << 17) | (8u << 24);
        const uint32_t aoff[12] = {XR_H, XR_L, XR_H, NXI_H, NXI_L, NXI_H,
                                   XR_H, XR_L, XR_H, XI_H,  XI_L,  XI_H};
        const uint32_t boff[12] = {WR_H, WR_H, WR_L, WI_H, WI_H, WI_L,
                                   WI_H, WI_H, WI_L, WR_H, WR_H, WR_L};
        for (int it = 0; it < 8; ++it) {
            int s = it & 1;
            MBARRIER_WAIT_PARITY(sb + MB_FULL(s), (it >> 1) & 1);
            if (elect_one_pred()) {
                uint32_t stage = sb + STAGE_BASE(s);
#pragma unroll
                for (int g = 0; g < 12; ++g) {
                    uint64_t ad = make_desc_sw64(stage + aoff[g]);
                    uint64_t bd = make_desc_sw64(stage + boff[g]);
                    uint32_t dreg = tmem + ((g >= 6) ? 256 : 0);
#pragma unroll
                    for (int kk = 0; kk < 2; ++kk) {
                        uint32_t en = !(it == 0 && kk == 0 && (g == 0 || g == 6));
                        mma_f16_ss_cg1(dreg, ad + kk * 2, bd + kk * 2, IDESC, en);
                    }
                }
                TCGEN05_COMMIT((it == 7) ? (sb + MB_DONE) : (sb + MB_EMPTY(s)));
            }
        }
    }
    // warps 6,7: fall through to epilogue wait

    // ---- epilogue: WG0 -> re plane (cols 0-255), WG1 -> im plane (cols 256-511)
    MBARRIER_WAIT_PARITY(sb + MB_DONE, 0);
    TCGEN05_FENCE_AFTER();
    {
        int wg = tid >> 7;
        int wt = tid & 127;
        int m = m0 + wt;
        float* dst = out + (size_t)wg * BB * NN + (size_t)m * NN;
        uint32_t colbase = tmem + wg * 256;
#pragma unroll
        for (int c = 0; c < 8; ++c) {
            uint32_t r[32];
            TCGEN05_LD_32X32B_X32(r, colbase + c * 32);
            TCGEN05_WAIT_LD();
            float4* d4 = (float4*)(dst + c * 32);
#pragma unroll
            for (int q = 0; q < 8; ++q)
                d4[q] = make_float4(__uint_as_float(r[4 * q]), __uint_as_float(r[4 * q + 1]),
                                    __uint_as_float(r[4 * q + 2]), __uint_as_float(r[4 * q + 3]));
        }
    }
    __syncthreads();
    if (wid == 4) {
        TCGEN05_RELINQ();
        TCGEN05_DEALLOC(tmem, 512);
    }
#endif  // HAS_TC
}

// ---------------- launch ----------------
extern "C" void kernel_launch(void* const* d_in, const int* in_sizes, int n_in,
                              void* d_out, int out_size) {
    const float* x_re  = (const float*)d_in[0];
    const float* x_im  = (const float*)d_in[1];
    const float* theta = (const float*)d_in[2];
    const float* phi   = (const float*)d_in[3];
    const float* gamma = (const float*)d_in[4];
    float* out = (float*)d_out;

    cudaFuncSetAttribute(gemm_tc_kernel, cudaFuncAttributeMaxDynamicSharedMemorySize, SMEM_TOTAL);

    coeff_kernel<<<LL, NN>>>(theta, phi);
    build_w_kernel<<<NN / RB, NN>>>(gamma);
    probe_kernel<<<1, 32>>>();
    gemm_tc_kernel<<<BB / 128, 256, SMEM_TOTAL>>>(x_re, x_im, out);
}

// round 7
// speedup vs baseline: 1.2978x; 1.0533x over previous
#include <cuda_runtime.h>
#include <cuda_bf16.h>
#include <cstdint>

#define NN 256
#define LL 256
#define BB 16384

#if defined(__CUDA_ARCH_FEAT_SM103_ALL) || defined(__CUDA_ARCH_FEAT_SM100_ALL) || defined(__CUDA_ARCH_FEAT_SM101_ALL)
#define HAS_TC 1
#else
#define HAS_TC 0
#endif

typedef unsigned long long u64;

// ---------------- scratch ----------------
__device__ float2 g_DG[LL * NN];   // [l][n] — coalesced
__device__ float2 g_OP[LL * NN];   // partner-indexed: g_OP[l][i] multiplies x_perm[i^1]
// Deduplicated B images: Wr/Wi bf16 hi/lo as pre-swizzled 16KB SMEM tile images per 32-k chunk.
__device__ __align__(128) __nv_bfloat16 g_Wrh[256 * 256];
__device__ __align__(128) __nv_bfloat16 g_Wrl[256 * 256];
__device__ __align__(128) __nv_bfloat16 g_Wih[256 * 256];
__device__ __align__(128) __nv_bfloat16 g_Wil[256 * 256];

// ---------------- common helpers ----------------
__device__ __forceinline__ uint32_t smem_u32(const void* p) {
    uint32_t a;
    asm("{ .reg .u64 t; cvta.to.shared.u64 t, %1; cvt.u32.u64 %0, t; }" : "=r"(a) : "l"(p));
    return a;
}
__device__ __forceinline__ float2 cmul(float2 a, float2 b) {
    return make_float2(a.x * b.x - a.y * b.y, a.x * b.y + a.y * b.x);
}
union BU { __nv_bfloat162 h; uint32_t u; };
union F2U { float2 f; u64 u; };

#define FMA_F32X2(d, a, b) \
    asm("fma.rn.f32x2 %0, %1, %2, %0;" : "+l"(d) : "l"(a), "l"(b))
#define MUL_F32X2(d, a, b) \
    asm("mul.rn.f32x2 %0, %1, %2;" : "=l"(d) : "l"(a), "l"(b))
__device__ __forceinline__ u64 pack2(float lo, float hi) {
    u64 r; asm("mov.b64 %0, {%1,%2};" : "=l"(r) : "f"(lo), "f"(hi)); return r;
}
__device__ __forceinline__ u64 dup2(float x) {
    u64 r; asm("mov.b64 %0, {%1,%1};" : "=l"(r) : "f"(x)); return r;
}

// ---------------- tcgen05 / async helpers ----------------
#define TCGEN05_ALLOC(sa, n) \
    asm volatile("tcgen05.alloc.cta_group::1.sync.aligned.shared::cta.b32 [%0], %1;" :: "r"((uint32_t)(sa)), "r"((uint32_t)(n)) : "memory")
#define TCGEN05_DEALLOC(t, n) \
    asm volatile("tcgen05.dealloc.cta_group::1.sync.aligned.b32 %0, %1;" :: "r"(t), "r"((uint32_t)(n)))
#define TCGEN05_RELINQ() \
    asm volatile("tcgen05.relinquish_alloc_permit.cta_group::1.sync.aligned;")
#define TCGEN05_COMMIT(mb) \
    asm volatile("tcgen05.commit.cta_group::1.mbarrier::arrive::one.shared::cluster.b64 [%0];" :: "r"((uint32_t)(mb)) : "memory")
#define TCGEN05_WAIT_LD() asm volatile("tcgen05.wait::ld.sync.aligned;" ::: "memory")
#define TCGEN05_FENCE_AFTER() asm volatile("tcgen05.fence::after_thread_sync;" ::: "memory")
#define FENCE_ASYNC_SHARED() asm volatile("fence.proxy.async.shared::cta;" ::: "memory")

#define MBARRIER_INIT(mb, cnt) \
    asm volatile("mbarrier.init.shared.b64 [%0], %1;" :: "r"((uint32_t)(mb)), "r"((uint32_t)(cnt)) : "memory")
#define MBARRIER_ARRIVE(mb) \
    asm volatile("mbarrier.arrive.shared.b64 _, [%0];" :: "r"((uint32_t)(mb)) : "memory")
#define MBARRIER_EXPECT_TX(mb, tx) \
    asm volatile("mbarrier.arrive.expect_tx.shared.b64 _, [%0], %1;" :: "r"((uint32_t)(mb)), "r"((uint32_t)(tx)) : "memory")
#define MBARRIER_WAIT_PARITY(mb, ph) do { \
    uint32_t _mb = (uint32_t)(mb), _ph = (uint32_t)(ph), _done; \
    asm volatile("{\n\t.reg .pred p;\n\tmbarrier.try_wait.parity.acquire.cta.shared::cta.b64 p, [%1], %2;\n\tselp.b32 %0, 1, 0, p;\n\t}" \
        : "=r"(_done) : "r"(_mb), "r"(_ph) : "memory"); \
    if (!_done) { \
        asm volatile("{\n\t.reg .pred P1;\n\tWL_%=:\n\tmbarrier.try_wait.parity.acquire.cta.shared::cta.b64 P1, [%0], %1, 0x989680;\n\t@P1 bra.uni WD_%=;\n\tbra.uni WL_%=;\n\tWD_%=:\n\t}" \
            :: "r"(_mb), "r"(_ph) : "memory"); \
    } } while (0)

#define CP_ASYNC_BULK(dst, src, bytes, mb) \
    asm volatile("cp.async.bulk.shared::cluster.global.mbarrier::complete_tx::bytes [%0], [%1], %2, [%3];" \
        :: "r"((uint32_t)(dst)), "l"(src), "r"((uint32_t)(bytes)), "r"((uint32_t)(mb)) : "memory")

#define TCGEN05_LD_32X32B_X32(r, ta) \
    asm volatile("tcgen05.ld.sync.aligned.32x32b.x32.b32 " \
        "{%0,%1,%2,%3,%4,%5,%6,%7,%8,%9,%10,%11,%12,%13,%14,%15," \
        "%16,%17,%18,%19,%20,%21,%22,%23,%24,%25,%26,%27,%28,%29,%30,%31}, [%32];" \
        : "=r"((r)[0]), "=r"((r)[1]), "=r"((r)[2]), "=r"((r)[3]), "=r"((r)[4]), "=r"((r)[5]), "=r"((r)[6]), "=r"((r)[7]), \
          "=r"((r)[8]), "=r"((r)[9]), "=r"((r)[10]), "=r"((r)[11]), "=r"((r)[12]), "=r"((r)[13]), "=r"((r)[14]), "=r"((r)[15]), \
          "=r"((r)[16]), "=r"((r)[17]), "=r"((r)[18]), "=r"((r)[19]), "=r"((r)[20]), "=r"((r)[21]), "=r"((r)[22]), "=r"((r)[23]), \
          "=r"((r)[24]), "=r"((r)[25]), "=r"((r)[26]), "=r"((r)[27]), "=r"((r)[28]), "=r"((r)[29]), "=r"((r)[30]), "=r"((r)[31]) \
        : "r"(ta))

#define SWZ64(o) ((o) ^ (((o) >> 3) & 0x30))

#if HAS_TC
__device__ __forceinline__ uint32_t elect_one_pred() {
    uint32_t p;
    asm volatile("{\n\t.reg .pred p;\n\telect.sync _|p, 0xFFFFFFFF;\n\tselp.b32 %0, 1, 0, p;\n\t}" : "=r"(p));
    return p;
}
// SW64 K-major descriptor: layout=4, version=1, SBO=32 (512B per 8-row group), LBO=1 (16B)
__device__ __forceinline__ uint64_t make_desc_sw64(uint32_t base) {
    return ((uint64_t)4 << 61) | ((uint64_t)1 << 46) | ((uint64_t)32 << 32) | ((uint64_t)1 << 16)
         | (uint64_t)((base >> 4) & 0x3FFF);
}
__device__ __forceinline__ void mma_f16_ss_cg1(uint32_t d, uint64_t ad, uint64_t bd,
                                               uint32_t idesc, uint32_t en) {
    asm volatile(
        "{\n\t.reg .pred p;\n\tsetp.ne.u32 p, %5, 0;\n\t"
        "tcgen05.mma.cta_group::1.kind::f16 [%0], %1, %2, %3, {%4,%4,%4,%4}, p;\n\t}"
        :: "r"(d), "l"(ad), "l"(bd), "r"(idesc), "r"(0u), "r"(en) : "memory");
}
#endif

// ---------------- kernel 1: per-layer MZI coefficients ----------------
__global__ void coeff_kernel(const float* __restrict__ theta,
                             const float* __restrict__ phi) {
    __shared__ float2 ips[NN];
    __shared__ float2 eps[NN];
    int l = blockIdx.x;
    int n = threadIdx.x;
    const float* th = theta + l * (NN / 2);
    const float* ph = phi + l * (NN / 2);

    {
        float ang = 0.5f * th[n >> 1];
        if (n & 1) ang = -ang;
        float s, c; sincosf(ang, &s, &c);
        ips[n] = make_float2(c, s);
        if (n & 1) eps[n] = make_float2(1.f, 0.f);
        else { float s2, c2; sincosf(ph[n >> 1], &s2, &c2); eps[n] = make_float2(c2, s2); }
    }
    __syncthreads();

    int nm = (n - 1) & (NN - 1), np = (n + 1) & (NN - 1);
    float2 p0 = ips[nm], p1 = ips[n], p2 = ips[np];
    float2 v = make_float2(2.f * p1.x - p2.x - p0.x, 2.f * p1.y - p2.y - p0.y);
    float2 u = make_float2(2.f * p1.x + p2.x + p0.x, 2.f * p1.y + p2.y + p0.y);
    float2 en = eps[n], ep = eps[nm];

    float2 diag = cmul(en, v); diag.x *= 0.25f; diag.y *= 0.25f;
    float2 iu = make_float2(-u.y, u.x);
    float2 off = cmul(ep, iu); off.x *= 0.25f; off.y *= 0.25f;

    g_DG[l * NN + n] = diag;
    g_OP[l * NN + (n ^ 1)] = off;
}

// ---------------- kernel 2: compose W — fused layer pairs (1 barrier / 2 layers) ----
// Layers: l=0 (s=0) alone; pairs (2p+1, 2p+2) with (s1,s2)=(+1,-1) for p=0..126;
// l=255 (s=+1) alone; final right-perm shift -1.
#define RB 2
__global__ __launch_bounds__(NN) void build_w_kernel(const float* __restrict__ gamma) {
    __shared__ float2 bufA[RB][NN];
    __shared__ float2 bufB[RB][NN];
    int i = threadIdx.x;
    int r0 = blockIdx.x * RB;

#pragma unroll
    for (int r = 0; r < RB; r++) {
        int j = r0 + r;
        float2 v = make_float2(0.f, 0.f);
        if (i == j) { float s, c; sincosf(gamma[j], &s, &c); v = make_float2(c, s); }
        bufA[r][i] = v;
    }

    // loop-invariant indices (all pairs share s1=+1, s2=-1)
    const int M = NN - 1;
    int odd = i & 1;
    int xa1 = odd ? (i + 1) & M : (i - 1) & M;   // mid_a second operand
    int xb0 = odd ? (i - 1) & M : (i + 1) & M;   // mid_b first operand
    int xb1 = odd ? (i - 2) & M : (i + 2) & M;   // mid_b second operand
    int ca = (i - 1) & M;                        // layer-l1 coeff index for mid_a
    int cb = odd ? (i - 2) & M : i;              // layer-l1 coeff index for mid_b

    // layer 0 coeffs + tail-layer coeffs prefetched up front
    float2 d0 = g_DG[i], o0 = g_OP[i];
    float2 dL = g_DG[255 * NN + i], oL = g_OP[255 * NN + i];

    // 2-deep pair-coeff queue
    float2 qd1a[2], qo1a[2], qd1b[2], qo1b[2], qd2[2], qo2[2];
#pragma unroll
    for (int p = 0; p < 2; p++) {
        const float2* L1 = g_DG + (2 * p + 1) * NN;
        const float2* P1 = g_OP + (2 * p + 1) * NN;
        qd1a[p] = L1[ca]; qo1a[p] = P1[ca];
        qd1b[p] = L1[cb]; qo1b[p] = P1[cb];
        qd2[p] = g_DG[(2 * p + 2) * NN + i];
        qo2[p] = g_OP[(2 * p + 2) * NN + i];
    }
    __syncthreads();

    float2 (*A)[NN] = bufA;
    float2 (*Bx)[NN] = bufB;

    // ---- layer 0 (s=0)
    {
        u64 D1 = pack2(d0.x, d0.y), D2 = pack2(-d0.y, d0.x);
        u64 O1 = pack2(o0.x, o0.y), O2 = pack2(-o0.y, o0.x);
#pragma unroll
        for (int r = 0; r < RB; r++) {
            float2 t = A[r][i], u = A[r][i ^ 1];
            u64 w;
            MUL_F32X2(w, dup2(t.x), D1);
            FMA_F32X2(w, dup2(t.y), D2);
            FMA_F32X2(w, dup2(u.x), O1);
            FMA_F32X2(w, dup2(u.y), O2);
            F2U cv; cv.u = w; Bx[r][i] = cv.f;
        }
        __syncthreads();
        float2 (*tmp)[NN] = A; A = Bx; Bx = tmp;
    }

    // ---- 127 fused pairs
    for (int p = 0; p < 127; ++p) {
        int sl = p & 1;
        float2 d1a = qd1a[sl], o1a = qo1a[sl], d1b = qd1b[sl], o1b = qo1b[sl];
        float2 d2c = qd2[sl], o2c = qo2[sl];
        if (p + 2 < 127) {   // refill slot with pair p+2
            int pp = p + 2;
            const float2* L1 = g_DG + (2 * pp + 1) * NN;
            const float2* P1 = g_OP + (2 * pp + 1) * NN;
            qd1a[sl] = L1[ca]; qo1a[sl] = P1[ca];
            qd1b[sl] = L1[cb]; qo1b[sl] = P1[cb];
            qd2[sl] = g_DG[(2 * pp + 2) * NN + i];
            qo2[sl] = g_OP[(2 * pp + 2) * NN + i];
        }
        u64 A1 = pack2(d1a.x, d1a.y), A2 = pack2(-d1a.y, d1a.x);
        u64 Oa1 = pack2(o1a.x, o1a.y), Oa2 = pack2(-o1a.y, o1a.x);
        u64 B1 = pack2(d1b.x, d1b.y), B2 = pack2(-d1b.y, d1b.x);
        u64 Ob1 = pack2(o1b.x, o1b.y), Ob2 = pack2(-o1b.y, o1b.x);
        u64 D1 = pack2(d2c.x, d2c.y), D2 = pack2(-d2c.y, d2c.x);
        u64 Q1 = pack2(o2c.x, o2c.y), Q2 = pack2(-o2c.y, o2c.x);
#pragma unroll
        for (int r = 0; r < RB; r++) {
            float2 va0 = A[r][i],  va1 = A[r][xa1];
            float2 vb0 = A[r][xb0], vb1 = A[r][xb1];
            u64 ma, mb, w;
            MUL_F32X2(ma, dup2(va0.x), A1);
            FMA_F32X2(ma, dup2(va0.y), A2);
            FMA_F32X2(ma, dup2(va1.x), Oa1);
            FMA_F32X2(ma, dup2(va1.y), Oa2);
            MUL_F32X2(mb, dup2(vb0.x), B1);
            FMA_F32X2(mb, dup2(vb0.y), B2);
            FMA_F32X2(mb, dup2(vb1.x), Ob1);
            FMA_F32X2(mb, dup2(vb1.y), Ob2);
            F2U fa; fa.u = ma; F2U fb; fb.u = mb;
            MUL_F32X2(w, dup2(fa.f.x), D1);
            FMA_F32X2(w, dup2(fa.f.y), D2);
            FMA_F32X2(w, dup2(fb.f.x), Q1);
            FMA_F32X2(w, dup2(fb.f.y), Q2);
            F2U cv; cv.u = w; Bx[r][i] = cv.f;
        }
        __syncthreads();
        float2 (*tmp)[NN] = A; A = Bx; Bx = tmp;
    }

    // ---- layer 255 (s=+1)
    {
        int ia = (i + 1) & M;
        int ib = ((i ^ 1) + 1) & M;
        u64 D1 = pack2(dL.x, dL.y), D2 = pack2(-dL.y, dL.x);
        u64 O1 = pack2(oL.x, oL.y), O2 = pack2(-oL.y, oL.x);
#pragma unroll
        for (int r = 0; r < RB; r++) {
            float2 t = A[r][ia], u = A[r][ib];
            u64 w;
            MUL_F32X2(w, dup2(t.x), D1);
            FMA_F32X2(w, dup2(t.y), D2);
            FMA_F32X2(w, dup2(u.x), O1);
            FMA_F32X2(w, dup2(u.y), O2);
            F2U cv; cv.u = w; Bx[r][i] = cv.f;
        }
        __syncthreads();
        float2 (*tmp)[NN] = A; A = Bx; Bx = tmp;
    }

    // store element (n=i, k=r0+r) of Wr/Wi into pre-swizzled 32-k chunk images
    auto store_b = [](__nv_bfloat16* img, int n, int k, __nv_bfloat16 v) {
        uint32_t off = ((uint32_t)k >> 5) * 16384u + SWZ64((uint32_t)(n * 64 + (k & 31) * 2));
        *(__nv_bfloat16*)((char*)img + off) = v;
    };

    int src = (i - 1) & M;
#pragma unroll
    for (int r = 0; r < RB; r++) {
        float2 w = A[r][src];        // W[k][n], k = r0+r, n = i
        int k = r0 + r, n = i;
        __nv_bfloat16 hr = __float2bfloat16(w.x);
        __nv_bfloat16 lr = __float2bfloat16(w.x - __bfloat162float(hr));
        __nv_bfloat16 hi = __float2bfloat16(w.y);
        __nv_bfloat16 li = __float2bfloat16(w.y - __bfloat162float(hi));
        store_b(g_Wrh, n, k, hr);
        store_b(g_Wrl, n, k, lr);
        store_b(g_Wih, n, k, hi);
        store_b(g_Wil, n, k, li);
    }
}

// ---------------- kernel 2.5: no-op spacer (keeps ncu capture on gemm) ----------------
__global__ void probe_kernel() {}

// ---------------- kernel 3: tcgen05 bf16-split GEMM, deduped B ----------------
#define KC 32
#define SMEM_TMEM 0
#define MB_FULL(s)  (16 + (s) * 8)
#define MB_EMPTY(s) (32 + (s) * 8)
#define MB_DONE     48
#define XR_H 0
#define XR_L 8192
#define XI_H 16384
#define XI_L 24576
#define NXI_H 32768
#define NXI_L 40960
#define WR_H 49152
#define WR_L 65536
#define WI_H 81920
#define WI_L 98304
#define STAGE_SZ 114688
#define STAGE_BASE(s) (1024 + (s) * STAGE_SZ)
#define SMEM_TOTAL (1024 + 2 * STAGE_SZ)

__global__ __launch_bounds__(256, 1)
void gemm_tc_kernel(const float* __restrict__ xre, const float* __restrict__ xim,
                    float* __restrict__ out) {
#if HAS_TC
    extern __shared__ char smem[];
    const uint32_t sb = smem_u32(smem);
    int tid = threadIdx.x, wid = tid >> 5, lane = tid & 31;
    int m0 = blockIdx.x * 128;

    if (wid == 7) TCGEN05_ALLOC(sb + SMEM_TMEM, 512);
    if (tid == 0) {
        MBARRIER_INIT(sb + MB_FULL(0), 7);   // 6 A-warps + B expect_tx arrive
        MBARRIER_INIT(sb + MB_FULL(1), 7);
        MBARRIER_INIT(sb + MB_EMPTY(0), 1);
        MBARRIER_INIT(sb + MB_EMPTY(1), 1);
        MBARRIER_INIT(sb + MB_DONE, 1);
    }
    __syncthreads();
    uint32_t tmem;
    asm volatile("ld.shared.b32 %0, [%1];" : "=r"(tmem) : "r"(sb + SMEM_TMEM));

    if (wid < 6) {
        // ---- A producer (6 warps): X fp32 -> bf16 hi/lo (+negated Xi), strided split
        for (int it = 0; it < 8; ++it) {
            int s = it & 1;
            if (it >= 2) MBARRIER_WAIT_PARITY(sb + MB_EMPTY(s), ((it >> 1) - 1) & 1);
            int kc = it * KC;
            uint32_t stage = sb + STAGE_BASE(s);
            for (int g = tid; g < 2048; g += 192) {
                int pl = g >> 10;
                int rr = (g >> 3) & 127;
                int f4 = g & 7;
                const float* plane = pl ? xim : xre;
                float4 v = *(const float4*)(plane + (size_t)(m0 + rr) * NN + kc + f4 * 4);
                BU h0, h1, l0, l1;
                h0.h = __floats2bfloat162_rn(v.x, v.y);
                h1.h = __floats2bfloat162_rn(v.z, v.w);
                float2 f0 = __bfloat1622float2(h0.h), f1 = __bfloat1622float2(h1.h);
                l0.h = __floats2bfloat162_rn(v.x - f0.x, v.y - f0.y);
                l1.h = __floats2bfloat162_rn(v.z - f1.x, v.w - f1.y);
                uint32_t off = SWZ64((uint32_t)(rr * 64 + f4 * 8));
                uint32_t hdst = stage + (pl ? XI_H : XR_H) + off;
                uint32_t ldst = stage + (pl ? XI_L : XR_L) + off;
                asm volatile("st.shared.v2.b32 [%0], {%1,%2};" :: "r"(hdst), "r"(h0.u), "r"(h1.u) : "memory");
                asm volatile("st.shared.v2.b32 [%0], {%1,%2};" :: "r"(ldst), "r"(l0.u), "r"(l1.u) : "memory");
                if (pl) {
                    uint32_t nh0 = h0.u ^ 0x80008000u, nh1 = h1.u ^ 0x80008000u;
                    uint32_t nl0 = l0.u ^ 0x80008000u, nl1 = l1.u ^ 0x80008000u;
                    asm volatile("st.shared.v2.b32 [%0], {%1,%2};" :: "r"(stage + NXI_H + off), "r"(nh0), "r"(nh1) : "memory");
                    asm volatile("st.shared.v2.b32 [%0], {%1,%2};" :: "r"(stage + NXI_L + off), "r"(nl0), "r"(nl1) : "memory");
                }
            }
            FENCE_ASYNC_SHARED();
            __syncwarp();
            if (lane == 0) MBARRIER_ARRIVE(sb + MB_FULL(s));
        }
    } else if (wid == 6) {
        // ---- B producer: 4 bulk copies (16KB) per stage from pre-swizzled chunk images
        for (int it = 0; it < 8; ++it) {
            int s = it & 1;
            if (it >= 2) MBARRIER_WAIT_PARITY(sb + MB_EMPTY(s), ((it >> 1) - 1) & 1);
            if (elect_one_pred()) {
                uint32_t mb = sb + MB_FULL(s);
                uint32_t stage = sb + STAGE_BASE(s);
                size_t co = (size_t)it * 16384;
                MBARRIER_EXPECT_TX(mb, 65536);
                CP_ASYNC_BULK(stage + WR_H, (const char*)g_Wrh + co, 16384, mb);
                CP_ASYNC_BULK(stage + WR_L, (const char*)g_Wrl + co, 16384, mb);
                CP_ASYNC_BULK(stage + WI_H, (const char*)g_Wih + co, 16384, mb);
                CP_ASYNC_BULK(stage + WI_L, (const char*)g_Wil + co, 16384, mb);
            }
        }
    } else {
        // ---- MMA warp (wid 7): 12 groups/stage; D0=Yr, D1=Yi. Descs = base + const.
        const uint32_t IDESC = (1u << 4) | (1u << 7) | (1u << 10) | (32u << 17) | (8u << 24);
        const uint32_t aoff[12] = {XR_H, XR_L, XR_H, NXI_H, NXI_L, NXI_H,
                                   XR_H, XR_L, XR_H, XI_H,  XI_L,  XI_H};
        const uint32_t boff[12] = {WR_H, WR_H, WR_L, WI_H, WI_H, WI_L,
                                   WI_H, WI_H, WI_L, WR_H, WR_H, WR_L};
        uint64_t dbase0 = make_desc_sw64(sb + STAGE_BASE(0));
        uint64_t dbase1 = make_desc_sw64(sb + STAGE_BASE(1));
        for (int it = 0; it < 8; ++it) {
            int s = it & 1;
            MBARRIER_WAIT_PARITY(sb + MB_FULL(s), (it >> 1) & 1);
            if (elect_one_pred()) {
                uint64_t dbase = s ? dbase1 : dbase0;
#pragma unroll
                for (int g = 0; g < 12; ++g) {
                    uint64_t ad = dbase + (aoff[g] >> 4);
                    uint64_t bd = dbase + (boff[g] >> 4);
                    uint32_t dreg = tmem + ((g >= 6) ? 256 : 0);
#pragma unroll
                    for (int kk = 0; kk < 2; ++kk) {
                        uint32_t en = !(it == 0 && kk == 0 && (g == 0 || g == 6));
                        mma_f16_ss_cg1(dreg, ad + kk * 2, bd + kk * 2, IDESC, en);
                    }
                }
                TCGEN05_COMMIT((it == 7) ? (sb + MB_DONE) : (sb + MB_EMPTY(s)));
            }
        }
    }

    // ---- epilogue: WG0 -> re plane (cols 0-255), WG1 -> im plane (cols 256-511)
    MBARRIER_WAIT_PARITY(sb + MB_DONE, 0);
    TCGEN05_FENCE_AFTER();
    {
        int wg = tid >> 7;
        int wt = tid & 127;
        int m = m0 + wt;
        float* dst = out + (size_t)wg * BB * NN + (size_t)m * NN;
        uint32_t colbase = tmem + wg * 256;
#pragma unroll
        for (int c = 0; c < 8; ++c) {
            uint32_t r[32];
            TCGEN05_LD_32X32B_X32(r, colbase + c * 32);
            TCGEN05_WAIT_LD();
            float4* d4 = (float4*)(dst + c * 32);
#pragma unroll
            for (int q = 0; q < 8; ++q)
                d4[q] = make_float4(__uint_as_float(r[4 * q]), __uint_as_float(r[4 * q + 1]),
                                    __uint_as_float(r[4 * q + 2]), __uint_as_float(r[4 * q + 3]));
        }
    }
    __syncthreads();
    if (wid == 7) {
        TCGEN05_RELINQ();
        TCGEN05_DEALLOC(tmem, 512);
    }
#endif  // HAS_TC
}

// ---------------- launch ----------------
extern "C" void kernel_launch(void* const* d_in, const int* in_sizes, int n_in,
                              void* d_out, int out_size) {
    const float* x_re  = (const float*)d_in[0];
    const float* x_im  = (const float*)d_in[1];
    const float* theta = (const float*)d_in[2];
    const float* phi   = (const float*)d_in[3];
    const float* gamma = (const float*)d_in[4];
    float* out = (float*)d_out;

    cudaFuncSetAttribute(gemm_tc_kernel, cudaFuncAttributeMaxDynamicSharedMemorySize, SMEM_TOTAL);

    coeff_kernel<<<LL, NN>>>(theta, phi);
    build_w_kernel<<<NN / RB, NN>>>(gamma);
    probe_kernel<<<1, 32>>>();
    gemm_tc_kernel<<<BB / 128, 256, SMEM_TOTAL>>>(x_re, x_im, out);
}

// round 8
// speedup vs baseline: 1.3523x; 1.0420x over previous
#include <cuda_runtime.h>
#include <cuda_bf16.h>
#include <cstdint>

#define NN 256
#define LL 256
#define BB 16384

#if defined(__CUDA_ARCH_FEAT_SM103_ALL) || defined(__CUDA_ARCH_FEAT_SM100_ALL) || defined(__CUDA_ARCH_FEAT_SM101_ALL)
#define HAS_TC 1
#else
#define HAS_TC 0
#endif

typedef unsigned long long u64;

// ---------------- scratch ----------------
// packed coeffs: g_C[l][n] = (diag.x, diag.y, off.x, off.y), off partner-indexed
__device__ float4 g_C[LL * NN];
// Deduplicated B images: Wr/Wi bf16 hi/lo as pre-swizzled 16KB SMEM tile images per 32-k chunk.
__device__ __align__(128) __nv_bfloat16 g_Wrh[256 * 256];
__device__ __align__(128) __nv_bfloat16 g_Wrl[256 * 256];
__device__ __align__(128) __nv_bfloat16 g_Wih[256 * 256];
__device__ __align__(128) __nv_bfloat16 g_Wil[256 * 256];

// ---------------- common helpers ----------------
__device__ __forceinline__ uint32_t smem_u32(const void* p) {
    uint32_t a;
    asm("{ .reg .u64 t; cvta.to.shared.u64 t, %1; cvt.u32.u64 %0, t; }" : "=r"(a) : "l"(p));
    return a;
}
__device__ __forceinline__ float2 cmul(float2 a, float2 b) {
    return make_float2(a.x * b.x - a.y * b.y, a.x * b.y + a.y * b.x);
}
union BU { __nv_bfloat162 h; uint32_t u; };
union F2U { float2 f; u64 u; };

#define FMA_F32X2(d, a, b) \
    asm("fma.rn.f32x2 %0, %1, %2, %0;" : "+l"(d) : "l"(a), "l"(b))
#define MUL_F32X2(d, a, b) \
    asm("mul.rn.f32x2 %0, %1, %2;" : "=l"(d) : "l"(a), "l"(b))
__device__ __forceinline__ u64 pack2(float lo, float hi) {
    u64 r; asm("mov.b64 %0, {%1,%2};" : "=l"(r) : "f"(lo), "f"(hi)); return r;
}
__device__ __forceinline__ u64 dup2(float x) {
    u64 r; asm("mov.b64 %0, {%1,%1};" : "=l"(r) : "f"(x)); return r;
}

// ---------------- tcgen05 / async helpers ----------------
#define TCGEN05_ALLOC(sa, n) \
    asm volatile("tcgen05.alloc.cta_group::1.sync.aligned.shared::cta.b32 [%0], %1;" :: "r"((uint32_t)(sa)), "r"((uint32_t)(n)) : "memory")
#define TCGEN05_DEALLOC(t, n) \
    asm volatile("tcgen05.dealloc.cta_group::1.sync.aligned.b32 %0, %1;" :: "r"(t), "r"((uint32_t)(n)))
#define TCGEN05_RELINQ() \
    asm volatile("tcgen05.relinquish_alloc_permit.cta_group::1.sync.aligned;")
#define TCGEN05_COMMIT(mb) \
    asm volatile("tcgen05.commit.cta_group::1.mbarrier::arrive::one.shared::cluster.b64 [%0];" :: "r"((uint32_t)(mb)) : "memory")
#define TCGEN05_WAIT_LD() asm volatile("tcgen05.wait::ld.sync.aligned;" ::: "memory")
#define TCGEN05_FENCE_AFTER() asm volatile("tcgen05.fence::after_thread_sync;" ::: "memory")
#define FENCE_ASYNC_SHARED() asm volatile("fence.proxy.async.shared::cta;" ::: "memory")

#define MBARRIER_INIT(mb, cnt) \
    asm volatile("mbarrier.init.shared.b64 [%0], %1;" :: "r"((uint32_t)(mb)), "r"((uint32_t)(cnt)) : "memory")
#define MBARRIER_ARRIVE(mb) \
    asm volatile("mbarrier.arrive.shared.b64 _, [%0];" :: "r"((uint32_t)(mb)) : "memory")
#define MBARRIER_EXPECT_TX(mb, tx) \
    asm volatile("mbarrier.arrive.expect_tx.shared.b64 _, [%0], %1;" :: "r"((uint32_t)(mb)), "r"((uint32_t)(tx)) : "memory")
#define MBARRIER_WAIT_PARITY(mb, ph) do { \
    uint32_t _mb = (uint32_t)(mb), _ph = (uint32_t)(ph), _done; \
    asm volatile("{\n\t.reg .pred p;\n\tmbarrier.try_wait.parity.acquire.cta.shared::cta.b64 p, [%1], %2;\n\tselp.b32 %0, 1, 0, p;\n\t}" \
        : "=r"(_done) : "r"(_mb), "r"(_ph) : "memory"); \
    if (!_done) { \
        asm volatile("{\n\t.reg .pred P1;\n\tWL_%=:\n\tmbarrier.try_wait.parity.acquire.cta.shared::cta.b64 P1, [%0], %1, 0x989680;\n\t@P1 bra.uni WD_%=;\n\tbra.uni WL_%=;\n\tWD_%=:\n\t}" \
            :: "r"(_mb), "r"(_ph) : "memory"); \
    } } while (0)

#define CP_ASYNC_BULK(dst, src, bytes, mb) \
    asm volatile("cp.async.bulk.shared::cluster.global.mbarrier::complete_tx::bytes [%0], [%1], %2, [%3];" \
        :: "r"((uint32_t)(dst)), "l"(src), "r"((uint32_t)(bytes)), "r"((uint32_t)(mb)) : "memory")

#define TCGEN05_LD_32X32B_X32(r, ta) \
    asm volatile("tcgen05.ld.sync.aligned.32x32b.x32.b32 " \
        "{%0,%1,%2,%3,%4,%5,%6,%7,%8,%9,%10,%11,%12,%13,%14,%15," \
        "%16,%17,%18,%19,%20,%21,%22,%23,%24,%25,%26,%27,%28,%29,%30,%31}, [%32];" \
        : "=r"((r)[0]), "=r"((r)[1]), "=r"((r)[2]), "=r"((r)[3]), "=r"((r)[4]), "=r"((r)[5]), "=r"((r)[6]), "=r"((r)[7]), \
          "=r"((r)[8]), "=r"((r)[9]), "=r"((r)[10]), "=r"((r)[11]), "=r"((r)[12]), "=r"((r)[13]), "=r"((r)[14]), "=r"((r)[15]), \
          "=r"((r)[16]), "=r"((r)[17]), "=r"((r)[18]), "=r"((r)[19]), "=r"((r)[20]), "=r"((r)[21]), "=r"((r)[22]), "=r"((r)[23]), \
          "=r"((r)[24]), "=r"((r)[25]), "=r"((r)[26]), "=r"((r)[27]), "=r"((r)[28]), "=r"((r)[29]), "=r"((r)[30]), "=r"((r)[31]) \
        : "r"(ta))

#define SWZ64(o) ((o) ^ (((o) >> 3) & 0x30))

#if HAS_TC
__device__ __forceinline__ uint32_t elect_one_pred() {
    uint32_t p;
    asm volatile("{\n\t.reg .pred p;\n\telect.sync _|p, 0xFFFFFFFF;\n\tselp.b32 %0, 1, 0, p;\n\t}" : "=r"(p));
    return p;
}
// SW64 K-major descriptor: layout=4, version=1, SBO=32 (512B per 8-row group), LBO=1 (16B)
__device__ __forceinline__ uint64_t make_desc_sw64(uint32_t base) {
    return ((uint64_t)4 << 61) | ((uint64_t)1 << 46) | ((uint64_t)32 << 32) | ((uint64_t)1 << 16)
         | (uint64_t)((base >> 4) & 0x3FFF);
}
__device__ __forceinline__ void mma_f16_ss_cg1(uint32_t d, uint64_t ad, uint64_t bd,
                                               uint32_t idesc, uint32_t en) {
    asm volatile(
        "{\n\t.reg .pred p;\n\tsetp.ne.u32 p, %5, 0;\n\t"
        "tcgen05.mma.cta_group::1.kind::f16 [%0], %1, %2, %3, {%4,%4,%4,%4}, p;\n\t}"
        :: "r"(d), "l"(ad), "l"(bd), "r"(idesc), "r"(0u), "r"(en) : "memory");
}
#endif

// ---------------- kernel 1: per-layer MZI coefficients (packed output) ----------------
__global__ void coeff_kernel(const float* __restrict__ theta,
                             const float* __restrict__ phi) {
    __shared__ float2 ips[NN];
    __shared__ float2 eps[NN];
    __shared__ float2 offs[NN];
    int l = blockIdx.x;
    int n = threadIdx.x;
    const float* th = theta + l * (NN / 2);
    const float* ph = phi + l * (NN / 2);

    {
        float ang = 0.5f * th[n >> 1];
        if (n & 1) ang = -ang;
        float s, c; sincosf(ang, &s, &c);
        ips[n] = make_float2(c, s);
        if (n & 1) eps[n] = make_float2(1.f, 0.f);
        else { float s2, c2; sincosf(ph[n >> 1], &s2, &c2); eps[n] = make_float2(c2, s2); }
    }
    __syncthreads();

    int nm = (n - 1) & (NN - 1), np = (n + 1) & (NN - 1);
    float2 p0 = ips[nm], p1 = ips[n], p2 = ips[np];
    float2 v = make_float2(2.f * p1.x - p2.x - p0.x, 2.f * p1.y - p2.y - p0.y);
    float2 u = make_float2(2.f * p1.x + p2.x + p0.x, 2.f * p1.y + p2.y + p0.y);
    float2 en = eps[n], ep = eps[nm];

    float2 diag = cmul(en, v); diag.x *= 0.25f; diag.y *= 0.25f;
    float2 iu = make_float2(-u.y, u.x);
    float2 off = cmul(ep, iu); off.x *= 0.25f; off.y *= 0.25f;

    offs[n ^ 1] = off;       // partner-index the off coefficient
    __syncthreads();
    float2 o = offs[n];
    g_C[l * NN + n] = make_float4(diag.x, diag.y, o.x, o.y);
}

// ---------------- kernel 2: compose W — fused layer pairs, packed coeffs ----------------
#define RB 2
__global__ __launch_bounds__(NN) void build_w_kernel(const float* __restrict__ gamma) {
    __shared__ float2 bufA[RB][NN];
    __shared__ float2 bufB[RB][NN];
    int i = threadIdx.x;
    int r0 = blockIdx.x * RB;

#pragma unroll
    for (int r = 0; r < RB; r++) {
        int j = r0 + r;
        float2 v = make_float2(0.f, 0.f);
        if (i == j) { float s, c; sincosf(gamma[j], &s, &c); v = make_float2(c, s); }
        bufA[r][i] = v;
    }

    // loop-invariant indices (all pairs share s1=+1, s2=-1)
    const int M = NN - 1;
    int odd = i & 1;
    int xa1 = odd ? (i + 1) & M : (i - 1) & M;
    int xb0 = odd ? (i - 1) & M : (i + 1) & M;
    int xb1 = odd ? (i - 2) & M : (i + 2) & M;
    int ca = (i - 1) & M;
    int cb = odd ? (i - 2) & M : i;

    float4 c0 = g_C[i];
    float4 cL = g_C[255 * NN + i];

    // 2-deep pair-coeff queue (packed float4s)
    float4 qa[2], qb[2], q2[2];
#pragma unroll
    for (int p = 0; p < 2; p++) {
        qa[p] = g_C[(2 * p + 1) * NN + ca];
        qb[p] = g_C[(2 * p + 1) * NN + cb];
        q2[p] = g_C[(2 * p + 2) * NN + i];
    }
    __syncthreads();

    float2 (*A)[NN] = bufA;
    float2 (*Bx)[NN] = bufB;

    // ---- layer 0 (s=0)
    {
        u64 D1 = pack2(c0.x, c0.y), D2 = pack2(-c0.y, c0.x);
        u64 O1 = pack2(c0.z, c0.w), O2 = pack2(-c0.w, c0.z);
#pragma unroll
        for (int r = 0; r < RB; r++) {
            float2 t = A[r][i], u = A[r][i ^ 1];
            u64 w;
            MUL_F32X2(w, dup2(t.x), D1);
            FMA_F32X2(w, dup2(t.y), D2);
            FMA_F32X2(w, dup2(u.x), O1);
            FMA_F32X2(w, dup2(u.y), O2);
            F2U cv; cv.u = w; Bx[r][i] = cv.f;
        }
        __syncthreads();
        float2 (*tmp)[NN] = A; A = Bx; Bx = tmp;
    }

    // ---- 127 fused pairs
    for (int p = 0; p < 127; ++p) {
        int sl = p & 1;
        float4 a4 = qa[sl], b4 = qb[sl], d4 = q2[sl];
        if (p + 2 < 127) {
            int pp = p + 2;
            qa[sl] = g_C[(2 * pp + 1) * NN + ca];
            qb[sl] = g_C[(2 * pp + 1) * NN + cb];
            q2[sl] = g_C[(2 * pp + 2) * NN + i];
        }
        u64 A1 = pack2(a4.x, a4.y), A2 = pack2(-a4.y, a4.x);
        u64 Oa1 = pack2(a4.z, a4.w), Oa2 = pack2(-a4.w, a4.z);
        u64 B1 = pack2(b4.x, b4.y), B2 = pack2(-b4.y, b4.x);
        u64 Ob1 = pack2(b4.z, b4.w), Ob2 = pack2(-b4.w, b4.z);
        u64 D1 = pack2(d4.x, d4.y), D2 = pack2(-d4.y, d4.x);
        u64 Q1 = pack2(d4.z, d4.w), Q2 = pack2(-d4.w, d4.z);
#pragma unroll
        for (int r = 0; r < RB; r++) {
            float2 va0 = A[r][i],  va1 = A[r][xa1];
            float2 vb0 = A[r][xb0], vb1 = A[r][xb1];
            u64 ma, mb, w;
            MUL_F32X2(ma, dup2(va0.x), A1);
            FMA_F32X2(ma, dup2(va0.y), A2);
            FMA_F32X2(ma, dup2(va1.x), Oa1);
            FMA_F32X2(ma, dup2(va1.y), Oa2);
            MUL_F32X2(mb, dup2(vb0.x), B1);
            FMA_F32X2(mb, dup2(vb0.y), B2);
            FMA_F32X2(mb, dup2(vb1.x), Ob1);
            FMA_F32X2(mb, dup2(vb1.y), Ob2);
            F2U fa; fa.u = ma; F2U fb; fb.u = mb;
            MUL_F32X2(w, dup2(fa.f.x), D1);
            FMA_F32X2(w, dup2(fa.f.y), D2);
            FMA_F32X2(w, dup2(fb.f.x), Q1);
            FMA_F32X2(w, dup2(fb.f.y), Q2);
            F2U cv; cv.u = w; Bx[r][i] = cv.f;
        }
        __syncthreads();
        float2 (*tmp)[NN] = A; A = Bx; Bx = tmp;
    }

    // ---- layer 255 (s=+1)
    {
        int ia = (i + 1) & M;
        int ib = ((i ^ 1) + 1) & M;
        u64 D1 = pack2(cL.x, cL.y), D2 = pack2(-cL.y, cL.x);
        u64 O1 = pack2(cL.z, cL.w), O2 = pack2(-cL.w, cL.z);
#pragma unroll
        for (int r = 0; r < RB; r++) {
            float2 t = A[r][ia], u = A[r][ib];
            u64 w;
            MUL_F32X2(w, dup2(t.x), D1);
            FMA_F32X2(w, dup2(t.y), D2);
            FMA_F32X2(w, dup2(u.x), O1);
            FMA_F32X2(w, dup2(u.y), O2);
            F2U cv; cv.u = w; Bx[r][i] = cv.f;
        }
        __syncthreads();
        float2 (*tmp)[NN] = A; A = Bx; Bx = tmp;
    }

    auto store_b = [](__nv_bfloat16* img, int n, int k, __nv_bfloat16 v) {
        uint32_t off = ((uint32_t)k >> 5) * 16384u + SWZ64((uint32_t)(n * 64 + (k & 31) * 2));
        *(__nv_bfloat16*)((char*)img + off) = v;
    };

    int src = (i - 1) & M;
#pragma unroll
    for (int r = 0; r < RB; r++) {
        float2 w = A[r][src];        // W[k][n], k = r0+r, n = i
        int k = r0 + r, n = i;
        __nv_bfloat16 hr = __float2bfloat16(w.x);
        __nv_bfloat16 lr = __float2bfloat16(w.x - __bfloat162float(hr));
        __nv_bfloat16 hi = __float2bfloat16(w.y);
        __nv_bfloat16 li = __float2bfloat16(w.y - __bfloat162float(hi));
        store_b(g_Wrh, n, k, hr);
        store_b(g_Wrl, n, k, lr);
        store_b(g_Wih, n, k, hi);
        store_b(g_Wil, n, k, li);
    }
}

// ---------------- kernel 2.5: no-op spacer (keeps ncu capture on gemm) ----------------
__global__ void probe_kernel() {}

// ---------------- kernel 3: tcgen05 bf16-split GEMM, register-prefetched A ----------------
#define KC 32
#define SMEM_TMEM 0
#define MB_FULL(s)  (16 + (s) * 8)
#define MB_EMPTY(s) (32 + (s) * 8)
#define MB_DONE     48
#define XR_H 0
#define XR_L 8192
#define XI_H 16384
#define XI_L 24576
#define NXI_H 32768
#define NXI_L 40960
#define WR_H 49152
#define WR_L 65536
#define WI_H 81920
#define WI_L 98304
#define STAGE_SZ 114688
#define STAGE_BASE(s) (1024 + (s) * STAGE_SZ)
#define SMEM_TOTAL (1024 + 2 * STAGE_SZ)

__global__ __launch_bounds__(256, 1)
void gemm_tc_kernel(const float* __restrict__ xre, const float* __restrict__ xim,
                    float* __restrict__ out) {
#if HAS_TC
    extern __shared__ char smem[];
    const uint32_t sb = smem_u32(smem);
    int tid = threadIdx.x, wid = tid >> 5, lane = tid & 31;
    int m0 = blockIdx.x * 128;

    if (wid == 4) TCGEN05_ALLOC(sb + SMEM_TMEM, 512);
    if (tid == 0) {
        MBARRIER_INIT(sb + MB_FULL(0), 5);   // 4 A-warps + B expect_tx arrive
        MBARRIER_INIT(sb + MB_FULL(1), 5);
        MBARRIER_INIT(sb + MB_EMPTY(0), 1);
        MBARRIER_INIT(sb + MB_EMPTY(1), 1);
        MBARRIER_INIT(sb + MB_DONE, 1);
    }
    __syncthreads();
    uint32_t tmem;
    asm volatile("ld.shared.b32 %0, [%1];" : "=r"(tmem) : "r"(sb + SMEM_TMEM));

    if (wid < 4) {
        // ---- A producer (4 warps, 128 threads): register-prefetched pipeline.
        // Group j (0..15): pl = j>>3 (plane), g = (j&7)*128 + tid, row rr = g>>3,
        // float4 f4 = g&7. LDGs for stage it+1 are issued DURING stage it, i.e.
        // before the next empty-wait — DRAM latency hides behind the MMA stage.
        float4 buf[16];
#pragma unroll
        for (int j = 0; j < 16; ++j) {
            int pl = j >> 3;
            int g = (j & 7) * 128 + tid;
            int rr = g >> 3, f4 = g & 7;
            const float* plane = pl ? xim : xre;
            buf[j] = *(const float4*)(plane + (size_t)(m0 + rr) * NN + f4 * 4);
        }
        for (int it = 0; it < 8; ++it) {
            int s = it & 1;
            if (it >= 2) MBARRIER_WAIT_PARITY(sb + MB_EMPTY(s), ((it >> 1) - 1) & 1);
            uint32_t stage = sb + STAGE_BASE(s);
            int kcn = (it + 1) * KC;
            bool more = (it < 7);
#pragma unroll
            for (int j = 0; j < 16; ++j) {
                int pl = j >> 3;
                int g = (j & 7) * 128 + tid;
                int rr = g >> 3, f4 = g & 7;
                float4 v = buf[j];
                if (more) {   // issue next stage's LDG immediately (registers only)
                    const float* plane = pl ? xim : xre;
                    buf[j] = *(const float4*)(plane + (size_t)(m0 + rr) * NN + kcn + f4 * 4);
                }
                BU h0, h1, l0, l1;
                h0.h = __floats2bfloat162_rn(v.x, v.y);
                h1.h = __floats2bfloat162_rn(v.z, v.w);
                float2 f0 = __bfloat1622float2(h0.h), f1 = __bfloat1622float2(h1.h);
                l0.h = __floats2bfloat162_rn(v.x - f0.x, v.y - f0.y);
                l1.h = __floats2bfloat162_rn(v.z - f1.x, v.w - f1.y);
                uint32_t off = SWZ64((uint32_t)(rr * 64 + f4 * 8));
                uint32_t hdst = stage + (pl ? XI_H : XR_H) + off;
                uint32_t ldst = stage + (pl ? XI_L : XR_L) + off;
                asm volatile("st.shared.v2.b32 [%0], {%1,%2};" :: "r"(hdst), "r"(h0.u), "r"(h1.u) : "memory");
                asm volatile("st.shared.v2.b32 [%0], {%1,%2};" :: "r"(ldst), "r"(l0.u), "r"(l1.u) : "memory");
                if (pl) {
                    uint32_t nh0 = h0.u ^ 0x80008000u, nh1 = h1.u ^ 0x80008000u;
                    uint32_t nl0 = l0.u ^ 0x80008000u, nl1 = l1.u ^ 0x80008000u;
                    asm volatile("st.shared.v2.b32 [%0], {%1,%2};" :: "r"(stage + NXI_H + off), "r"(nh0), "r"(nh1) : "memory");
                    asm volatile("st.shared.v2.b32 [%0], {%1,%2};" :: "r"(stage + NXI_L + off), "r"(nl0), "r"(nl1) : "memory");
                }
            }
            FENCE_ASYNC_SHARED();
            __syncwarp();
            if (lane == 0) MBARRIER_ARRIVE(sb + MB_FULL(s));
        }
    } else if (wid == 5) {
        // ---- B producer: 4 bulk copies (16KB) per stage from pre-swizzled chunk images
        for (int it = 0; it < 8; ++it) {
            int s = it & 1;
            if (it >= 2) MBARRIER_WAIT_PARITY(sb + MB_EMPTY(s), ((it >> 1) - 1) & 1);
            if (elect_one_pred()) {
                uint32_t mb = sb + MB_FULL(s);
                uint32_t stage = sb + STAGE_BASE(s);
                size_t co = (size_t)it * 16384;
                MBARRIER_EXPECT_TX(mb, 65536);
                CP_ASYNC_BULK(stage + WR_H, (const char*)g_Wrh + co, 16384, mb);
                CP_ASYNC_BULK(stage + WR_L, (const char*)g_Wrl + co, 16384, mb);
                CP_ASYNC_BULK(stage + WI_H, (const char*)g_Wih + co, 16384, mb);
                CP_ASYNC_BULK(stage + WI_L, (const char*)g_Wil + co, 16384, mb);
            }
        }
    } else if (wid == 4) {
        // ---- MMA warp: 12 groups/stage; D0=Yr, D1=Yi. Descs = stage base + const.
        const uint32_t IDESC = (1u << 4) | (1u << 7) | (1u << 10) | (32u << 17) | (8u << 24);
        const uint32_t aoff[12] = {XR_H, XR_L, XR_H, NXI_H, NXI_L, NXI_H,
                                   XR_H, XR_L, XR_H, XI_H,  XI_L,  XI_H};
        const uint32_t boff[12] = {WR_H, WR_H, WR_L, WI_H, WI_H, WI_L,
                                   WI_H, WI_H, WI_L, WR_H, WR_H, WR_L};
        uint64_t dbase0 = make_desc_sw64(sb + STAGE_BASE(0));
        uint64_t dbase1 = make_desc_sw64(sb + STAGE_BASE(1));
        for (int it = 0; it < 8; ++it) {
            int s = it & 1;
            MBARRIER_WAIT_PARITY(sb + MB_FULL(s), (it >> 1) & 1);
            if (elect_one_pred()) {
                uint64_t dbase = s ? dbase1 : dbase0;
#pragma unroll
                for (int g = 0; g < 12; ++g) {
                    uint64_t ad = dbase + (aoff[g] >> 4);
                    uint64_t bd = dbase + (boff[g] >> 4);
                    uint32_t dreg = tmem + ((g >= 6) ? 256 : 0);
#pragma unroll
                    for (int kk = 0; kk < 2; ++kk) {
                        uint32_t en = !(it == 0 && kk == 0 && (g == 0 || g == 6));
                        mma_f16_ss_cg1(dreg, ad + kk * 2, bd + kk * 2, IDESC, en);
                    }
                }
                TCGEN05_COMMIT((it == 7) ? (sb + MB_DONE) : (sb + MB_EMPTY(s)));
            }
        }
    }
    // warps 6,7: fall through to epilogue wait

    // ---- epilogue: WG0 -> re plane (cols 0-255), WG1 -> im plane (cols 256-511)
    MBARRIER_WAIT_PARITY(sb + MB_DONE, 0);
    TCGEN05_FENCE_AFTER();
    {
        int wg = tid >> 7;
        int wt = tid & 127;
        int m = m0 + wt;
        float* dst = out + (size_t)wg * BB * NN + (size_t)m * NN;
        uint32_t colbase = tmem + wg * 256;
#pragma unroll
        for (int c = 0; c < 8; ++c) {
            uint32_t r[32];
            TCGEN05_LD_32X32B_X32(r, colbase + c * 32);
            TCGEN05_WAIT_LD();
            float4* d4 = (float4*)(dst + c * 32);
#pragma unroll
            for (int q = 0; q < 8; ++q)
                d4[q] = make_float4(__uint_as_float(r[4 * q]), __uint_as_float(r[4 * q + 1]),
                                    __uint_as_float(r[4 * q + 2]), __uint_as_float(r[4 * q + 3]));
        }
    }
    __syncthreads();
    if (wid == 4) {
        TCGEN05_RELINQ();
        TCGEN05_DEALLOC(tmem, 512);
    }
#endif  // HAS_TC
}

// ---------------- launch ----------------
extern "C" void kernel_launch(void* const* d_in, const int* in_sizes, int n_in,
                              void* d_out, int out_size) {
    const float* x_re  = (const float*)d_in[0];
    const float* x_im  = (const float*)d_in[1];
    const float* theta = (const float*)d_in[2];
    const float* phi   = (const float*)d_in[3];
    const float* gamma = (const float*)d_in[4];
    float* out = (float*)d_out;

    cudaFuncSetAttribute(gemm_tc_kernel, cudaFuncAttributeMaxDynamicSharedMemorySize, SMEM_TOTAL);

    coeff_kernel<<<LL, NN>>>(theta, phi);
    build_w_kernel<<<NN / RB, NN>>>(gamma);
    probe_kernel<<<1, 32>>>();
    gemm_tc_kernel<<<BB / 128, 256, SMEM_TOTAL>>>(x_re, x_im, out);
}

// round 9
// speedup vs baseline: 1.3800x; 1.0205x over previous
#include <cuda_runtime.h>
#include <cuda_bf16.h>
#include <cstdint>

#define NN 256
#define LL 256
#define BB 16384

#if defined(__CUDA_ARCH_FEAT_SM103_ALL) || defined(__CUDA_ARCH_FEAT_SM100_ALL) || defined(__CUDA_ARCH_FEAT_SM101_ALL)
#define HAS_TC 1
#else
#define HAS_TC 0
#endif

typedef unsigned long long u64;

// ---------------- scratch ----------------
// packed coeffs: g_C[l][n] = (diag.x, diag.y, off.x, off.y), off partner-indexed
__device__ float4 g_C[LL * NN];
// Deduplicated B images: Wr/Wi bf16 hi/lo as pre-swizzled 16KB SMEM tile images per 32-k chunk.
__device__ __align__(128) __nv_bfloat16 g_Wrh[256 * 256];
__device__ __align__(128) __nv_bfloat16 g_Wrl[256 * 256];
__device__ __align__(128) __nv_bfloat16 g_Wih[256 * 256];
__device__ __align__(128) __nv_bfloat16 g_Wil[256 * 256];

// ---------------- common helpers ----------------
__device__ __forceinline__ uint32_t smem_u32(const void* p) {
    uint32_t a;
    asm("{ .reg .u64 t; cvta.to.shared.u64 t, %1; cvt.u32.u64 %0, t; }" : "=r"(a) : "l"(p));
    return a;
}
__device__ __forceinline__ float2 cmul(float2 a, float2 b) {
    return make_float2(a.x * b.x - a.y * b.y, a.x * b.y + a.y * b.x);
}
union BU { __nv_bfloat162 h; uint32_t u; };
union F2U { float2 f; u64 u; };

#define FMA_F32X2(d, a, b) \
    asm("fma.rn.f32x2 %0, %1, %2, %0;" : "+l"(d) : "l"(a), "l"(b))
#define MUL_F32X2(d, a, b) \
    asm("mul.rn.f32x2 %0, %1, %2;" : "=l"(d) : "l"(a), "l"(b))
__device__ __forceinline__ u64 pack2(float lo, float hi) {
    u64 r; asm("mov.b64 %0, {%1,%2};" : "=l"(r) : "f"(lo), "f"(hi)); return r;
}
__device__ __forceinline__ u64 dup2(float x) {
    u64 r; asm("mov.b64 %0, {%1,%1};" : "=l"(r) : "f"(x)); return r;
}

// ---------------- tcgen05 / async helpers ----------------
#define TCGEN05_ALLOC_CG2(sa, n) \
    asm volatile("tcgen05.alloc.cta_group::2.sync.aligned.shared::cta.b32 [%0], %1;" :: "r"((uint32_t)(sa)), "r"((uint32_t)(n)) : "memory")
#define TCGEN05_DEALLOC_CG2(t, n) \
    asm volatile("tcgen05.dealloc.cta_group::2.sync.aligned.b32 %0, %1;" :: "r"(t), "r"((uint32_t)(n)))
#define TCGEN05_RELINQ_CG2() \
    asm volatile("tcgen05.relinquish_alloc_permit.cta_group::2.sync.aligned;")
#define TCGEN05_COMMIT_MC_CG2(mb, mask) \
    asm volatile("tcgen05.commit.cta_group::2.mbarrier::arrive::one.shared::cluster.multicast::cluster.b64 [%0], %1;" \
        :: "r"((uint32_t)(mb)), "h"((uint16_t)(mask)) : "memory")
#define TCGEN05_WAIT_LD() asm volatile("tcgen05.wait::ld.sync.aligned;" ::: "memory")
#define TCGEN05_FENCE_AFTER() asm volatile("tcgen05.fence::after_thread_sync;" ::: "memory")
#define FENCE_ASYNC_SHARED() asm volatile("fence.proxy.async.shared::cta;" ::: "memory")
#define CLUSTER_SYNC() do { \
    asm volatile("barrier.cluster.arrive.aligned;" ::: "memory"); \
    asm volatile("barrier.cluster.wait.aligned;" ::: "memory"); \
} while (0)

#define MBARRIER_INIT(mb, cnt) \
    asm volatile("mbarrier.init.shared.b64 [%0], %1;" :: "r"((uint32_t)(mb)), "r"((uint32_t)(cnt)) : "memory")
#define MBARRIER_ARRIVE(mb) \
    asm volatile("mbarrier.arrive.shared.b64 _, [%0];" :: "r"((uint32_t)(mb)) : "memory")
// Arrive on leader CTA's mbarrier from either CTA of the cg2 pair (clears peer bit 24).
#define MBARRIER_ARRIVE_LEADER(mb) \
    asm volatile("{\n\t.reg .b32 la;\n\tand.b32 la, %0, 0xFEFFFFFF;\n\tmbarrier.arrive.shared::cluster.b64 _, [la];\n\t}" \
        :: "r"((uint32_t)(mb)) : "memory")
#define MBARRIER_EXPECT_TX(mb, tx) \
    asm volatile("mbarrier.arrive.expect_tx.shared.b64 _, [%0], %1;" :: "r"((uint32_t)(mb)), "r"((uint32_t)(tx)) : "memory")
#define MBARRIER_WAIT_PARITY(mb, ph) do { \
    uint32_t _mb = (uint32_t)(mb), _ph = (uint32_t)(ph), _done; \
    asm volatile("{\n\t.reg .pred p;\n\tmbarrier.try_wait.parity.acquire.cta.shared::cta.b64 p, [%1], %2;\n\tselp.b32 %0, 1, 0, p;\n\t}" \
        : "=r"(_done) : "r"(_mb), "r"(_ph) : "memory"); \
    if (!_done) { \
        asm volatile("{\n\t.reg .pred P1;\n\tWL_%=:\n\tmbarrier.try_wait.parity.acquire.cta.shared::cta.b64 P1, [%0], %1, 0x989680;\n\t@P1 bra.uni WD_%=;\n\tbra.uni WL_%=;\n\tWD_%=:\n\t}" \
            :: "r"(_mb), "r"(_ph) : "memory"); \
    } } while (0)
// Cluster-scope acquire wait: orders peer-CTA SMEM writes before MMA reads them.
#define MBARRIER_WAIT_PARITY_CLU(mb, ph) do { \
    uint32_t _mb = (uint32_t)(mb), _ph = (uint32_t)(ph), _done; \
    asm volatile("{\n\t.reg .pred p;\n\tmbarrier.try_wait.parity.acquire.cluster.shared::cta.b64 p, [%1], %2;\n\tselp.b32 %0, 1, 0, p;\n\t}" \
        : "=r"(_done) : "r"(_mb), "r"(_ph) : "memory"); \
    if (!_done) { \
        asm volatile("{\n\t.reg .pred P1;\n\tWL_%=:\n\tmbarrier.try_wait.parity.acquire.cluster.shared::cta.b64 P1, [%0], %1, 0x989680;\n\t@P1 bra.uni WD_%=;\n\tbra.uni WL_%=;\n\tWD_%=:\n\t}" \
            :: "r"(_mb), "r"(_ph) : "memory"); \
    } } while (0)

#define CP_ASYNC_BULK(dst, src, bytes, mb) \
    asm volatile("cp.async.bulk.shared::cluster.global.mbarrier::complete_tx::bytes [%0], [%1], %2, [%3];" \
        :: "r"((uint32_t)(dst)), "l"(src), "r"((uint32_t)(bytes)), "r"((uint32_t)(mb)) : "memory")

#define TCGEN05_LD_32X32B_X32(r, ta) \
    asm volatile("tcgen05.ld.sync.aligned.32x32b.x32.b32 " \
        "{%0,%1,%2,%3,%4,%5,%6,%7,%8,%9,%10,%11,%12,%13,%14,%15," \
        "%16,%17,%18,%19,%20,%21,%22,%23,%24,%25,%26,%27,%28,%29,%30,%31}, [%32];" \
        : "=r"((r)[0]), "=r"((r)[1]), "=r"((r)[2]), "=r"((r)[3]), "=r"((r)[4]), "=r"((r)[5]), "=r"((r)[6]), "=r"((r)[7]), \
          "=r"((r)[8]), "=r"((r)[9]), "=r"((r)[10]), "=r"((r)[11]), "=r"((r)[12]), "=r"((r)[13]), "=r"((r)[14]), "=r"((r)[15]), \
          "=r"((r)[16]), "=r"((r)[17]), "=r"((r)[18]), "=r"((r)[19]), "=r"((r)[20]), "=r"((r)[21]), "=r"((r)[22]), "=r"((r)[23]), \
          "=r"((r)[24]), "=r"((r)[25]), "=r"((r)[26]), "=r"((r)[27]), "=r"((r)[28]), "=r"((r)[29]), "=r"((r)[30]), "=r"((r)[31]) \
        : "r"(ta))

#define SWZ64(o) ((o) ^ (((o) >> 3) & 0x30))

#if HAS_TC
__device__ __forceinline__ uint32_t elect_one_pred() {
    uint32_t p;
    asm volatile("{\n\t.reg .pred p;\n\telect.sync _|p, 0xFFFFFFFF;\n\tselp.b32 %0, 1, 0, p;\n\t}" : "=r"(p));
    return p;
}
__device__ __forceinline__ uint32_t cluster_rank() {
    uint32_t r; asm("mov.u32 %0, %%cluster_ctarank;" : "=r"(r)); return r;
}
// SW64 K-major descriptor: layout=4, version=1, SBO=32 (512B per 8-row group), LBO=1 (16B)
__device__ __forceinline__ uint64_t make_desc_sw64(uint32_t base) {
    return ((uint64_t)4 << 61) | ((uint64_t)1 << 46) | ((uint64_t)32 << 32) | ((uint64_t)1 << 16)
         | (uint64_t)((base >> 4) & 0x3FFF);
}
// cg2 f16 MMA: M=256 across the pair, 8-reg disable mask (all lanes enabled)
__device__ __forceinline__ void mma_f16_ss_cg2(uint32_t d, uint64_t ad, uint64_t bd,
                                               uint32_t idesc, uint32_t en) {
    asm volatile(
        "{\n\t.reg .pred p;\n\tsetp.ne.u32 p, %5, 0;\n\t"
        "tcgen05.mma.cta_group::2.kind::f16 [%0], %1, %2, %3, {%4,%4,%4,%4,%4,%4,%4,%4}, p;\n\t}"
        :: "r"(d), "l"(ad), "l"(bd), "r"(idesc), "r"(0u), "r"(en) : "memory");
}
#endif

// ---------------- kernel 1: per-layer MZI coefficients (packed output) ----------------
__global__ void coeff_kernel(const float* __restrict__ theta,
                             const float* __restrict__ phi) {
    __shared__ float2 ips[NN];
    __shared__ float2 eps[NN];
    __shared__ float2 offs[NN];
    int l = blockIdx.x;
    int n = threadIdx.x;
    const float* th = theta + l * (NN / 2);
    const float* ph = phi + l * (NN / 2);

    {
        float ang = 0.5f * th[n >> 1];
        if (n & 1) ang = -ang;
        float s, c; sincosf(ang, &s, &c);
        ips[n] = make_float2(c, s);
        if (n & 1) eps[n] = make_float2(1.f, 0.f);
        else { float s2, c2; sincosf(ph[n >> 1], &s2, &c2); eps[n] = make_float2(c2, s2); }
    }
    __syncthreads();

    int nm = (n - 1) & (NN - 1), np = (n + 1) & (NN - 1);
    float2 p0 = ips[nm], p1 = ips[n], p2 = ips[np];
    float2 v = make_float2(2.f * p1.x - p2.x - p0.x, 2.f * p1.y - p2.y - p0.y);
    float2 u = make_float2(2.f * p1.x + p2.x + p0.x, 2.f * p1.y + p2.y + p0.y);
    float2 en = eps[n], ep = eps[nm];

    float2 diag = cmul(en, v); diag.x *= 0.25f; diag.y *= 0.25f;
    float2 iu = make_float2(-u.y, u.x);
    float2 off = cmul(ep, iu); off.x *= 0.25f; off.y *= 0.25f;

    offs[n ^ 1] = off;       // partner-index the off coefficient
    __syncthreads();
    float2 o = offs[n];
    g_C[l * NN + n] = make_float4(diag.x, diag.y, o.x, o.y);
}

// ---------------- kernel 2: compose W — fused layer pairs, packed coeffs ----------------
#define RB 2
__global__ __launch_bounds__(NN) void build_w_kernel(const float* __restrict__ gamma) {
    __shared__ float2 bufA[RB][NN];
    __shared__ float2 bufB[RB][NN];
    int i = threadIdx.x;
    int r0 = blockIdx.x * RB;

#pragma unroll
    for (int r = 0; r < RB; r++) {
        int j = r0 + r;
        float2 v = make_float2(0.f, 0.f);
        if (i == j) { float s, c; sincosf(gamma[j], &s, &c); v = make_float2(c, s); }
        bufA[r][i] = v;
    }

    // loop-invariant indices (all pairs share s1=+1, s2=-1)
    const int M = NN - 1;
    int odd = i & 1;
    int xa1 = odd ? (i + 1) & M : (i - 1) & M;
    int xb0 = odd ? (i - 1) & M : (i + 1) & M;
    int xb1 = odd ? (i - 2) & M : (i + 2) & M;
    int ca = (i - 1) & M;
    int cb = odd ? (i - 2) & M : i;

    float4 c0 = g_C[i];
    float4 cL = g_C[255 * NN + i];

    // 2-deep pair-coeff queue (packed float4s)
    float4 qa[2], qb[2], q2[2];
#pragma unroll
    for (int p = 0; p < 2; p++) {
        qa[p] = g_C[(2 * p + 1) * NN + ca];
        qb[p] = g_C[(2 * p + 1) * NN + cb];
        q2[p] = g_C[(2 * p + 2) * NN + i];
    }
    __syncthreads();

    float2 (*A)[NN] = bufA;
    float2 (*Bx)[NN] = bufB;

    // ---- layer 0 (s=0)
    {
        u64 D1 = pack2(c0.x, c0.y), D2 = pack2(-c0.y, c0.x);
        u64 O1 = pack2(c0.z, c0.w), O2 = pack2(-c0.w, c0.z);
#pragma unroll
        for (int r = 0; r < RB; r++) {
            float2 t = A[r][i], u = A[r][i ^ 1];
            u64 w;
            MUL_F32X2(w, dup2(t.x), D1);
            FMA_F32X2(w, dup2(t.y), D2);
            FMA_F32X2(w, dup2(u.x), O1);
            FMA_F32X2(w, dup2(u.y), O2);
            F2U cv; cv.u = w; Bx[r][i] = cv.f;
        }
        __syncthreads();
        float2 (*tmp)[NN] = A; A = Bx; Bx = tmp;
    }

    // ---- 127 fused pairs
    for (int p = 0; p < 127; ++p) {
        int sl = p & 1;
        float4 a4 = qa[sl], b4 = qb[sl], d4 = q2[sl];
        if (p + 2 < 127) {
            int pp = p + 2;
            qa[sl] = g_C[(2 * pp + 1) * NN + ca];
            qb[sl] = g_C[(2 * pp + 1) * NN + cb];
            q2[sl] = g_C[(2 * pp + 2) * NN + i];
        }
        u64 A1 = pack2(a4.x, a4.y), A2 = pack2(-a4.y, a4.x);
        u64 Oa1 = pack2(a4.z, a4.w), Oa2 = pack2(-a4.w, a4.z);
        u64 B1 = pack2(b4.x, b4.y), B2 = pack2(-b4.y, b4.x);
        u64 Ob1 = pack2(b4.z, b4.w), Ob2 = pack2(-b4.w, b4.z);
        u64 D1 = pack2(d4.x, d4.y), D2 = pack2(-d4.y, d4.x);
        u64 Q1 = pack2(d4.z, d4.w), Q2 = pack2(-d4.w, d4.z);
#pragma unroll
        for (int r = 0; r < RB; r++) {
            float2 va0 = A[r][i],  va1 = A[r][xa1];
            float2 vb0 = A[r][xb0], vb1 = A[r][xb1];
            u64 ma, mb, w;
            MUL_F32X2(ma, dup2(va0.x), A1);
            FMA_F32X2(ma, dup2(va0.y), A2);
            FMA_F32X2(ma, dup2(va1.x), Oa1);
            FMA_F32X2(ma, dup2(va1.y), Oa2);
            MUL_F32X2(mb, dup2(vb0.x), B1);
            FMA_F32X2(mb, dup2(vb0.y), B2);
            FMA_F32X2(mb, dup2(vb1.x), Ob1);
            FMA_F32X2(mb, dup2(vb1.y), Ob2);
            F2U fa; fa.u = ma; F2U fb; fb.u = mb;
            MUL_F32X2(w, dup2(fa.f.x), D1);
            FMA_F32X2(w, dup2(fa.f.y), D2);
            FMA_F32X2(w, dup2(fb.f.x), Q1);
            FMA_F32X2(w, dup2(fb.f.y), Q2);
            F2U cv; cv.u = w; Bx[r][i] = cv.f;
        }
        __syncthreads();
        float2 (*tmp)[NN] = A; A = Bx; Bx = tmp;
    }

    // ---- layer 255 (s=+1)
    {
        int ia = (i + 1) & M;
        int ib = ((i ^ 1) + 1) & M;
        u64 D1 = pack2(cL.x, cL.y), D2 = pack2(-cL.y, cL.x);
        u64 O1 = pack2(cL.z, cL.w), O2 = pack2(-cL.w, cL.z);
#pragma unroll
        for (int r = 0; r < RB; r++) {
            float2 t = A[r][ia], u = A[r][ib];
            u64 w;
            MUL_F32X2(w, dup2(t.x), D1);
            FMA_F32X2(w, dup2(t.y), D2);
            FMA_F32X2(w, dup2(u.x), O1);
            FMA_F32X2(w, dup2(u.y), O2);
            F2U cv; cv.u = w; Bx[r][i] = cv.f;
        }
        __syncthreads();
        float2 (*tmp)[NN] = A; A = Bx; Bx = tmp;
    }

    auto store_b = [](__nv_bfloat16* img, int n, int k, __nv_bfloat16 v) {
        uint32_t off = ((uint32_t)k >> 5) * 16384u + SWZ64((uint32_t)(n * 64 + (k & 31) * 2));
        *(__nv_bfloat16*)((char*)img + off) = v;
    };

    int src = (i - 1) & M;
#pragma unroll
    for (int r = 0; r < RB; r++) {
        float2 w = A[r][src];        // W[k][n], k = r0+r, n = i
        int k = r0 + r, n = i;
        __nv_bfloat16 hr = __float2bfloat16(w.x);
        __nv_bfloat16 lr = __float2bfloat16(w.x - __bfloat162float(hr));
        __nv_bfloat16 hi = __float2bfloat16(w.y);
        __nv_bfloat16 li = __float2bfloat16(w.y - __bfloat162float(hi));
        store_b(g_Wrh, n, k, hr);
        store_b(g_Wrl, n, k, lr);
        store_b(g_Wih, n, k, hi);
        store_b(g_Wil, n, k, li);
    }
}

// ---------------- kernel 2.5: no-op spacer (keeps ncu capture on gemm) ----------------
__global__ void probe_kernel() {}

// ---------------- kernel 3: tcgen05 cg2 (M=256) bf16-split GEMM ----------------
// 2-CTA clusters; cluster covers M=256 rows, D = [Yr | Yi] 512 TMEM cols.
// Per CTA per stage: A = its 128 rows (6 x 8KB tiles), B = its 128 n-rows (4 x 8KB).
#define KC 32
#define SMEM_TMEM 0
#define MB_FULL(s)  (16 + (s) * 8)   // local: 4 A-warps + B expect_tx
#define MB_EMPTY(s) (32 + (s) * 8)   // multicast from leader commit
#define MB_LEAD(s)  (48 + (s) * 8)   // on leader: 2 relay arrivals
#define MB_DONE     64               // multicast from final commit
#define XR_H 0
#define XR_L 8192
#define XI_H 16384
#define XI_L 24576
#define NXI_H 32768
#define NXI_L 40960
#define WR_H 49152
#define WR_L 57344
#define WI_H 65536
#define WI_L 73728
#define STAGE_SZ 81920
#define STAGE_BASE(s) (1024 + (s) * STAGE_SZ)
#define SMEM_TOTAL (1024 + 2 * STAGE_SZ)

__global__ __launch_bounds__(256, 1) __cluster_dims__(2, 1, 1)
void gemm_tc_kernel(const float* __restrict__ xre, const float* __restrict__ xim,
                    float* __restrict__ out) {
#if HAS_TC
    extern __shared__ char smem[];
    const uint32_t sb = smem_u32(smem);
    int tid = threadIdx.x, wid = tid >> 5, lane = tid & 31;
    int m0 = blockIdx.x * 128;             // this CTA's 128 batch rows
    uint32_t rank = cluster_rank();

    if (wid == 4) TCGEN05_ALLOC_CG2(sb + SMEM_TMEM, 512);
    if (tid == 0) {
        MBARRIER_INIT(sb + MB_FULL(0), 5);
        MBARRIER_INIT(sb + MB_FULL(1), 5);
        MBARRIER_INIT(sb + MB_EMPTY(0), 1);
        MBARRIER_INIT(sb + MB_EMPTY(1), 1);
        MBARRIER_INIT(sb + MB_LEAD(0), 2);
        MBARRIER_INIT(sb + MB_LEAD(1), 2);
        MBARRIER_INIT(sb + MB_DONE, 1);
    }
    __syncthreads();
    CLUSTER_SYNC();        // peer barrier inits visible before any cluster arrival
    uint32_t tmem;
    asm volatile("ld.shared.b32 %0, [%1];" : "=r"(tmem) : "r"(sb + SMEM_TMEM));

    if (wid < 4) {
        // ---- A producer (4 warps): register-prefetched fp32 -> bf16 hi/lo (+negated Xi)
        float4 buf[16];
#pragma unroll
        for (int j = 0; j < 16; ++j) {
            int pl = j >> 3;
            int g = (j & 7) * 128 + tid;
            int rr = g >> 3, f4 = g & 7;
            const float* plane = pl ? xim : xre;
            buf[j] = *(const float4*)(plane + (size_t)(m0 + rr) * NN + f4 * 4);
        }
        for (int it = 0; it < 8; ++it) {
            int s = it & 1;
            if (it >= 2) MBARRIER_WAIT_PARITY(sb + MB_EMPTY(s), ((it >> 1) - 1) & 1);
            uint32_t stage = sb + STAGE_BASE(s);
            int kcn = (it + 1) * KC;
            bool more = (it < 7);
#pragma unroll
            for (int j = 0; j < 16; ++j) {
                int pl = j >> 3;
                int g = (j & 7) * 128 + tid;
                int rr = g >> 3, f4 = g & 7;
                float4 v = buf[j];
                if (more) {
                    const float* plane = pl ? xim : xre;
                    buf[j] = *(const float4*)(plane + (size_t)(m0 + rr) * NN + kcn + f4 * 4);
                }
                BU h0, h1, l0, l1;
                h0.h = __floats2bfloat162_rn(v.x, v.y);
                h1.h = __floats2bfloat162_rn(v.z, v.w);
                float2 f0 = __bfloat1622float2(h0.h), f1 = __bfloat1622float2(h1.h);
                l0.h = __floats2bfloat162_rn(v.x - f0.x, v.y - f0.y);
                l1.h = __floats2bfloat162_rn(v.z - f1.x, v.w - f1.y);
                uint32_t off = SWZ64((uint32_t)(rr * 64 + f4 * 8));
                uint32_t hdst = stage + (pl ? XI_H : XR_H) + off;
                uint32_t ldst = stage + (pl ? XI_L : XR_L) + off;
                asm volatile("st.shared.v2.b32 [%0], {%1,%2};" :: "r"(hdst), "r"(h0.u), "r"(h1.u) : "memory");
                asm volatile("st.shared.v2.b32 [%0], {%1,%2};" :: "r"(ldst), "r"(l0.u), "r"(l1.u) : "memory");
                if (pl) {
                    uint32_t nh0 = h0.u ^ 0x80008000u, nh1 = h1.u ^ 0x80008000u;
                    uint32_t nl0 = l0.u ^ 0x80008000u, nl1 = l1.u ^ 0x80008000u;
                    asm volatile("st.shared.v2.b32 [%0], {%1,%2};" :: "r"(stage + NXI_H + off), "r"(nh0), "r"(nh1) : "memory");
                    asm volatile("st.shared.v2.b32 [%0], {%1,%2};" :: "r"(stage + NXI_L + off), "r"(nl0), "r"(nl1) : "memory");
                }
            }
            FENCE_ASYNC_SHARED();
            __syncwarp();
            if (lane == 0) MBARRIER_ARRIVE(sb + MB_FULL(s));
        }
    } else if (wid == 5) {
        // ---- B producer: this CTA's half of each image (rank-offset 8KB slices)
        for (int it = 0; it < 8; ++it) {
            int s = it & 1;
            if (it >= 2) MBARRIER_WAIT_PARITY(sb + MB_EMPTY(s), ((it >> 1) - 1) & 1);
            if (elect_one_pred()) {
                uint32_t mb = sb + MB_FULL(s);
                uint32_t stage = sb + STAGE_BASE(s);
                size_t co = (size_t)it * 16384 + (size_t)rank * 8192;
                MBARRIER_EXPECT_TX(mb, 32768);
                CP_ASYNC_BULK(stage + WR_H, (const char*)g_Wrh + co, 8192, mb);
                CP_ASYNC_BULK(stage + WR_L, (const char*)g_Wrl + co, 8192, mb);
                CP_ASYNC_BULK(stage + WI_H, (const char*)g_Wih + co, 8192, mb);
                CP_ASYNC_BULK(stage + WI_L, (const char*)g_Wil + co, 8192, mb);
            }
        }
    } else if (wid == 6) {
        // ---- relay: forward local stage readiness to leader's MB_LEAD
        for (int it = 0; it < 8; ++it) {
            int s = it & 1;
            MBARRIER_WAIT_PARITY(sb + MB_FULL(s), (it >> 1) & 1);
            if (elect_one_pred()) MBARRIER_ARRIVE_LEADER(sb + MB_LEAD(s));
        }
    } else if (wid == 4 && rank == 0) {
        // ---- MMA warp (leader only): cg2 M=256, 12 groups x 2 kk per stage
        const uint32_t IDESC = (1u << 4) | (1u << 7) | (1u << 10) | (32u << 17) | (16u << 24);
        const uint32_t aoff[12] = {XR_H, XR_L, XR_H, NXI_H, NXI_L, NXI_H,
                                   XR_H, XR_L, XR_H, XI_H,  XI_L,  XI_H};
        const uint32_t boff[12] = {WR_H, WR_H, WR_L, WI_H, WI_H, WI_L,
                                   WI_H, WI_H, WI_L, WR_H, WR_H, WR_L};
        uint64_t dbase0 = make_desc_sw64(sb + STAGE_BASE(0));
        uint64_t dbase1 = make_desc_sw64(sb + STAGE_BASE(1));
        for (int it = 0; it < 8; ++it) {
            int s = it & 1;
            MBARRIER_WAIT_PARITY_CLU(sb + MB_LEAD(s), (it >> 1) & 1);
            if (elect_one_pred()) {
                uint64_t dbase = s ? dbase1 : dbase0;
#pragma unroll
                for (int g = 0; g < 12; ++g) {
                    uint64_t ad = dbase + (aoff[g] >> 4);
                    uint64_t bd = dbase + (boff[g] >> 4);
                    uint32_t dreg = tmem + ((g >= 6) ? 256 : 0);
#pragma unroll
                    for (int kk = 0; kk < 2; ++kk) {
                        uint32_t en = !(it == 0 && kk == 0 && (g == 0 || g == 6));
                        mma_f16_ss_cg2(dreg, ad + kk * 2, bd + kk * 2, IDESC, en);
                    }
                }
                TCGEN05_COMMIT_MC_CG2((it == 7) ? (sb + MB_DONE) : (sb + MB_EMPTY(s)), 0x3);
            }
        }
    }
    // warp 7 (and rank1 warp 4): fall through to epilogue wait

    // ---- epilogue: each CTA writes its 128 rows; WG0 -> re plane, WG1 -> im plane
    MBARRIER_WAIT_PARITY(sb + MB_DONE, 0);
    TCGEN05_FENCE_AFTER();
    {
        int wg = tid >> 7;
        int wt = tid & 127;
        int m = m0 + wt;
        float* dst = out + (size_t)wg * BB * NN + (size_t)m * NN;
        uint32_t colbase = tmem + wg * 256;
#pragma unroll
        for (int c = 0; c < 8; ++c) {
            uint32_t r[32];
            TCGEN05_LD_32X32B_X32(r, colbase + c * 32);
            TCGEN05_WAIT_LD();
            float4* d4 = (float4*)(dst + c * 32);
#pragma unroll
            for (int q = 0; q < 8; ++q)
                d4[q] = make_float4(__uint_as_float(r[4 * q]), __uint_as_float(r[4 * q + 1]),
                                    __uint_as_float(r[4 * q + 2]), __uint_as_float(r[4 * q + 3]));
        }
    }
    __syncthreads();
    if (wid == 4) {
        TCGEN05_RELINQ_CG2();
        TCGEN05_DEALLOC_CG2(tmem, 512);
    }
    CLUSTER_SYNC();        // no CTA exits while peer ops may be in flight
#endif  // HAS_TC
}

// ---------------- launch ----------------
extern "C" void kernel_launch(void* const* d_in, const int* in_sizes, int n_in,
                              void* d_out, int out_size) {
    const float* x_re  = (const float*)d_in[0];
    const float* x_im  = (const float*)d_in[1];
    const float* theta = (const float*)d_in[2];
    const float* phi   = (const float*)d_in[3];
    const float* gamma = (const float*)d_in[4];
    float* out = (float*)d_out;

    cudaFuncSetAttribute(gemm_tc_kernel, cudaFuncAttributeMaxDynamicSharedMemorySize, SMEM_TOTAL);

    coeff_kernel<<<LL, NN>>>(theta, phi);
    build_w_kernel<<<NN / RB, NN>>>(gamma);
    probe_kernel<<<1, 32>>>();
    gemm_tc_kernel<<<BB / 128, 256, SMEM_TOTAL>>>(x_re, x_im, out);
}